// round 12
// baseline (speedup 1.0000x reference)
#include <cuda_runtime.h>
#include <math.h>

#define SEQ_LEN 8192
#define HIDDEN  768
#define BATCH   8
#define NFFT    8192     // packed complex FFT size
#define MFFT    16384    // real FFT size
#define SMEM_BYTES (NFFT * 8)   // 65536

// ---------------- static scratch (allocation-free rule) ----------------
__device__ float2 g_tw[NFFT];                         // exp(-2*pi*i*k/16384)
__device__ float  g_kT[HIDDEN * SEQ_LEN];             // filter transposed (D, L)
__device__ float2 g_Kf[HIDDEN * (NFFT + 1)];          // rfft(k)/16384 per d

__device__ __forceinline__ float2 cmul(float2 a, float2 b) {
    return make_float2(a.x * b.x - a.y * b.y, a.x * b.y + a.y * b.x);
}
__device__ __forceinline__ float2 cmulc(float2 a, float2 b) {   // a * conj(b)
    return make_float2(a.x * b.x + a.y * b.y, a.y * b.x - a.x * b.y);
}
__device__ __forceinline__ float2 csq(float2 a) {
    return make_float2(a.x * a.x - a.y * a.y, 2.0f * a.x * a.y);
}
__device__ __forceinline__ float2 mulni(float2 a) {  // a * (-i)
    return make_float2(a.y, -a.x);
}
// XOR-swizzled physical index: conflict-free for strided FFT passes and
// 2-way worst case for the bit-reversed pointwise pass.
__device__ __forceinline__ int PHYS(int i) {
    return (i & ~15) | ((i ^ (i >> 4) ^ (i >> 8)) & 15);
}

#define FBF(a, b, w) { float2 u_=(a), v_=(b); (a)=make_float2(u_.x+v_.x,u_.y+v_.y); \
                       float2 d_=make_float2(u_.x-v_.x,u_.y-v_.y); (b)=cmul(d_, (w)); }
#define FBF1(a, b)   { float2 u_=(a), v_=(b); (a)=make_float2(u_.x+v_.x,u_.y+v_.y); \
                       (b)=make_float2(u_.x-v_.x,u_.y-v_.y); }
#define FBFNI(a, b)  { float2 u_=(a), v_=(b); (a)=make_float2(u_.x+v_.x,u_.y+v_.y); \
                       (b)=make_float2(u_.y-v_.y, -(u_.x-v_.x)); }
#define IBF(a, b, w) { float2 u_=(a); float2 tv_=cmulc((b),(w)); \
                       (a)=make_float2(u_.x+tv_.x,u_.y+tv_.y); (b)=make_float2(u_.x-tv_.x,u_.y-tv_.y); }
#define IBF1(a, b)   FBF1(a, b)
#define IBFPI(a, b)  { float2 u_=(a), v_=(b); float2 tv_=make_float2(-v_.y, v_.x); \
                       (a)=make_float2(u_.x+tv_.x,u_.y+tv_.y); (b)=make_float2(u_.x-tv_.x,u_.y-tv_.y); }

#define C8f 0.70710678118654752f
#define CAf 0.92387953251128676f
#define CBf 0.38268343236508977f

// ---------------- twiddle init ----------------
__global__ void twiddle_init() {
    int k = blockIdx.x * blockDim.x + threadIdx.x;
    if (k < NFFT) {
        double a = -2.0 * M_PI * (double)k / (double)MFFT;
        g_tw[k] = make_float2((float)cos(a), (float)sin(a));
    }
}

// ---------------- shared forward stages 1,2 on an 8-group ----------------
__device__ __forceinline__ void fwd_stage12(float2* x, float2 w1) {
    float2 w2 = csq(w1);
    float2 w4 = csq(w2);
    float2 w2n = mulni(w2);
    FBF(x[0], x[2], w2);  FBF(x[1], x[3], w2n);
    FBF(x[4], x[6], w2);  FBF(x[5], x[7], w2n);
    FBF(x[0], x[1], w4);  FBF(x[2], x[3], w4);
    FBF(x[4], x[5], w4);  FBF(x[6], x[7], w4);
}
__device__ __forceinline__ void fwd_stage0_zero(float2* x, float2 w1) {
    // stage 0 with zero upper half: x[e+4] = x[e]*w(e)
    float2 wr1 = cmul(w1, make_float2(C8f, -C8f));
    float2 wr2 = mulni(w1);
    float2 wr3 = cmul(w1, make_float2(-C8f, -C8f));
    x[4] = cmul(x[0], w1);
    x[5] = cmul(x[1], wr1);
    x[6] = cmul(x[2], wr2);
    x[7] = cmul(x[3], wr3);
}

// ---------------- fused forward pass 1 (stages 0,1,2), contiguous source (kf) ---
__device__ __forceinline__ void fwd_pass1_fused(float2* S, int tid, const float2* __restrict__ g) {
#pragma unroll
    for (int it = 0; it < 2; it++) {
        int t = tid + it * 512;
        float2 x[8];
#pragma unroll
        for (int e = 0; e < 4; e++) x[e] = g[t + e * 1024];
        float2 w1 = g_tw[t << 1];
        fwd_stage0_zero(x, w1);
        fwd_stage12(x, w1);
#pragma unroll
        for (int e = 0; e < 8; e++) S[PHYS(t + e * 1024)] = x[e];
    }
}

// ---------------- fused forward pass 1, strided source (conv reads x directly) --
__device__ __forceinline__ void fwd_pass1_direct(float2* S, int tid, const float* __restrict__ xg) {
#pragma unroll
    for (int it = 0; it < 2; it++) {
        int t = tid + it * 512;
        float2 x[8];
#pragma unroll
        for (int e = 0; e < 4; e++) {
            int n = t + e * 1024;
            x[e] = make_float2(xg[(size_t)(2 * n) * HIDDEN],
                               xg[(size_t)(2 * n + 1) * HIDDEN]);
        }
        float2 w1 = g_tw[t << 1];
        fwd_stage0_zero(x, w1);
        fwd_stage12(x, w1);
#pragma unroll
        for (int e = 0; e < 8; e++) S[PHYS(t + e * 1024)] = x[e];
    }
}

// ---------------- grouped forward stages s, s+1, s+2 (s in {3,6}) ----------------
template<int s>
__device__ __forceinline__ void fwd_group3(float2* S, int tid) {
    const int h = 1 << (10 - s);
#pragma unroll
    for (int it = 0; it < 2; it++) {
        int t = tid + it * 512;
        int r = t & (h - 1);
        int base = ((t >> (10 - s)) << (13 - s)) | r;
        float2 x[8];
#pragma unroll
        for (int e = 0; e < 8; e++) x[e] = S[PHYS(base + e * h)];
        float2 w1 = g_tw[r << (s + 1)];
        {
            float2 wr1 = cmul(w1, make_float2(C8f, -C8f));
            float2 wr2 = mulni(w1);
            float2 wr3 = cmul(w1, make_float2(-C8f, -C8f));
            FBF(x[0], x[4], w1);
            FBF(x[1], x[5], wr1);
            FBF(x[2], x[6], wr2);
            FBF(x[3], x[7], wr3);
        }
        fwd_stage12(x, w1);
#pragma unroll
        for (int e = 0; e < 8; e++) S[PHYS(base + e * h)] = x[e];
    }
}

// ---------------- forward stages 9..12 on 16 consecutive elements ----------------
__device__ __forceinline__ void fwd_group16(float2* S, int tid) {
    float2* row = S + tid * 16;
    int hh = (tid ^ (tid >> 4)) & 15;        // PHYS(16*tid + e) = 16*tid + (e ^ hh)
    float2 x[16];
#pragma unroll
    for (int e = 0; e < 16; e++) x[e] = row[e ^ hh];
    FBF1 (x[0], x[8]);
    FBF  (x[1], x[9],  make_float2( CAf, -CBf));
    FBF  (x[2], x[10], make_float2( C8f, -C8f));
    FBF  (x[3], x[11], make_float2( CBf, -CAf));
    FBFNI(x[4], x[12]);
    FBF  (x[5], x[13], make_float2(-CBf, -CAf));
    FBF  (x[6], x[14], make_float2(-C8f, -C8f));
    FBF  (x[7], x[15], make_float2(-CAf, -CBf));
#pragma unroll
    for (int g = 0; g < 16; g += 8) {
        FBF1 (x[g+0], x[g+4]);
        FBF  (x[g+1], x[g+5], make_float2( C8f, -C8f));
        FBFNI(x[g+2], x[g+6]);
        FBF  (x[g+3], x[g+7], make_float2(-C8f, -C8f));
    }
#pragma unroll
    for (int g = 0; g < 16; g += 4) {
        FBF1 (x[g+0], x[g+2]);
        FBFNI(x[g+1], x[g+3]);
    }
#pragma unroll
    for (int g = 0; g < 16; g += 2) FBF1(x[g], x[g+1]);
#pragma unroll
    for (int e = 0; e < 16; e++) row[e ^ hh] = x[e];
}

// ---------------- inverse stages 0..3 on 16 consecutive elements ----------------
__device__ __forceinline__ void inv_group16(float2* S, int tid) {
    float2* row = S + tid * 16;
    int hh = (tid ^ (tid >> 4)) & 15;
    float2 x[16];
#pragma unroll
    for (int e = 0; e < 16; e++) x[e] = row[e ^ hh];
#pragma unroll
    for (int g = 0; g < 16; g += 2) IBF1(x[g], x[g+1]);
#pragma unroll
    for (int g = 0; g < 16; g += 4) {
        IBF1 (x[g+0], x[g+2]);
        IBFPI(x[g+1], x[g+3]);
    }
#pragma unroll
    for (int g = 0; g < 16; g += 8) {
        IBF1 (x[g+0], x[g+4]);
        IBF  (x[g+1], x[g+5], make_float2( C8f, -C8f));
        IBFPI(x[g+2], x[g+6]);
        IBF  (x[g+3], x[g+7], make_float2(-C8f, -C8f));
    }
    IBF1 (x[0], x[8]);
    IBF  (x[1], x[9],  make_float2( CAf, -CBf));
    IBF  (x[2], x[10], make_float2( C8f, -C8f));
    IBF  (x[3], x[11], make_float2( CBf, -CAf));
    IBFPI(x[4], x[12]);
    IBF  (x[5], x[13], make_float2(-CBf, -CAf));
    IBF  (x[6], x[14], make_float2(-C8f, -C8f));
    IBF  (x[7], x[15], make_float2(-CAf, -CBf));
#pragma unroll
    for (int e = 0; e < 16; e++) row[e ^ hh] = x[e];
}

// ---------------- grouped inverse stages s0, s0+1, s0+2 (s0 in {4,7}) -------
template<int s0>
__device__ __forceinline__ void inv_group3(float2* S, int tid) {
    const int h = 1 << s0;
#pragma unroll
    for (int it = 0; it < 2; it++) {
        int t = tid + it * 512;
        int r = t & (h - 1);
        int base = ((t >> s0) << (s0 + 3)) | r;
        float2 x[8];
#pragma unroll
        for (int e = 0; e < 8; e++) x[e] = S[PHYS(base + e * h)];
        float2 wB = g_tw[r << (11 - s0)];
        float2 wB2 = csq(wB);
        float2 wB4 = csq(wB2);
        IBF(x[0], x[1], wB4);
        IBF(x[2], x[3], wB4);
        IBF(x[4], x[5], wB4);
        IBF(x[6], x[7], wB4);
        {
            float2 w2n = mulni(wB2);
            IBF(x[0], x[2], wB2);
            IBF(x[1], x[3], w2n);
            IBF(x[4], x[6], wB2);
            IBF(x[5], x[7], w2n);
        }
        {
            float2 wr1 = cmul(wB, make_float2(C8f, -C8f));
            float2 wr2 = mulni(wB);
            float2 wr3 = cmul(wB, make_float2(-C8f, -C8f));
            IBF(x[0], x[4], wB);
            IBF(x[1], x[5], wr1);
            IBF(x[2], x[6], wr2);
            IBF(x[3], x[7], wr3);
        }
#pragma unroll
        for (int e = 0; e < 8; e++) S[PHYS(base + e * h)] = x[e];
    }
}

// ---------------- fused inverse final pass, direct strided store to out ---------
__device__ __forceinline__ void inv_final_direct(float2* S, int tid,
                                                 float* __restrict__ og,
                                                 float scale, float bv) {
#pragma unroll
    for (int it = 0; it < 2; it++) {
        int t = tid + it * 512;           // base = t, r = t (s0 = 10)
        float2 x[8];
#pragma unroll
        for (int e = 0; e < 8; e++) x[e] = S[PHYS(t + e * 1024)];
        float2 wB = g_tw[t << 1];
        float2 wB2 = csq(wB);
        float2 wB4 = csq(wB2);
        IBF(x[0], x[1], wB4);
        IBF(x[2], x[3], wB4);
        IBF(x[4], x[5], wB4);
        IBF(x[6], x[7], wB4);
        {
            float2 w2n = mulni(wB2);
            IBF(x[0], x[2], wB2);
            IBF(x[1], x[3], w2n);
            IBF(x[4], x[6], wB2);
            IBF(x[5], x[7], w2n);
        }
        {
            float2 wr1 = cmul(wB, make_float2(C8f, -C8f));
            float2 wr2 = mulni(wB);
            float2 wr3 = cmul(wB, make_float2(-C8f, -C8f));
            float2 t0 = cmulc(x[4], wB);
            float2 t1 = cmulc(x[5], wr1);
            float2 t2 = cmulc(x[6], wr2);
            float2 t3 = cmulc(x[7], wr3);
            x[0] = make_float2(x[0].x + t0.x, x[0].y + t0.y);
            x[1] = make_float2(x[1].x + t1.x, x[1].y + t1.y);
            x[2] = make_float2(x[2].x + t2.x, x[2].y + t2.y);
            x[3] = make_float2(x[3].x + t3.x, x[3].y + t3.y);
        }
#pragma unroll
        for (int e = 0; e < 4; e++) {
            int m = t + e * 1024;
            og[(size_t)(2 * m) * HIDDEN]     = x[e].x * scale + bv;
            og[(size_t)(2 * m + 1) * HIDDEN] = x[e].y * scale + bv;
        }
    }
}

// ---------------- implicit filter MLP + modulation, writes g_kT directly --------
// Dynamic smem: hA[16][64], hB[16][64], ktile[768][17]
__global__ void filter_kernel(
    const float* __restrict__ w_in,  const float* __restrict__ b_in,  const float* __restrict__ freq_in,
    const float* __restrict__ w_h0,  const float* __restrict__ b_h0,  const float* __restrict__ freq_h0,
    const float* __restrict__ w_h1,  const float* __restrict__ b_h1,  const float* __restrict__ freq_h1,
    const float* __restrict__ w_out)
{
    extern __shared__ float sm[];
    float* hA    = sm;              // 16*64
    float* hB    = sm + 1024;       // 16*64
    float* ktile = sm + 2048;       // 768*17
    int l0 = blockIdx.x * 16;
    int tid = threadIdx.x;

    for (int idx = tid; idx < 16 * 64; idx += 256) {
        int ll = idx >> 6, j = idx & 63;
        int l = l0 + ll;
        float t0 = (float)l / (float)(SEQ_LEN - 1);
        float ang = (float)(2.0 * M_PI * 1e-4 / (double)SEQ_LEN) * (float)l;
        float z1 = cosf(ang), z2 = -sinf(ang);
        float v = t0 * w_in[j] + z1 * w_in[64 + j] + z2 * w_in[128 + j] + b_in[j];
        hA[ll * 64 + j] = sinf(freq_in[j] * v);
    }
    __syncthreads();
    for (int idx = tid; idx < 16 * 64; idx += 256) {
        int ll = idx >> 6, j = idx & 63;
        float acc = b_h0[j];
#pragma unroll
        for (int i = 0; i < 64; i++) acc += hA[ll * 64 + i] * w_h0[i * 64 + j];
        hB[ll * 64 + j] = sinf(freq_h0[j] * acc);
    }
    __syncthreads();
    for (int idx = tid; idx < 16 * 64; idx += 256) {
        int ll = idx >> 6, j = idx & 63;
        float acc = b_h1[j];
#pragma unroll
        for (int i = 0; i < 64; i++) acc += hB[ll * 64 + i] * w_h1[i * 64 + j];
        hA[ll * 64 + j] = sinf(freq_h1[j] * acc);
    }
    __syncthreads();

    const float MIND = 3.0701134573253943f;
    const float MAXD = 15.350567286626972f;
    for (int ll = 0; ll < 16; ll++) {
        int l = l0 + ll;
        float t0 = (float)l / (float)(SEQ_LEN - 1);
        for (int d = tid; d < HIDDEN; d += 256) {
            float acc = 0.f;
#pragma unroll
            for (int i = 0; i < 64; i++) acc += hA[ll * 64 + i] * w_out[i * HIDDEN + d];
            float ad = MIND + (MAXD - MIND) * ((float)d / 767.0f);
            ktile[d * 17 + ll] = acc * expf(-t0 * ad);
        }
    }
    __syncthreads();

    // write 768 rows of 16 floats each (64 B contiguous per row) as 4x float4
#pragma unroll
    for (int j = 0; j < 3; j++) {
        int row = j * 256 + tid;
        const float* kr = ktile + row * 17;
        float* dst = g_kT + (size_t)row * SEQ_LEN + l0;
        *reinterpret_cast<float4*>(dst)      = make_float4(kr[0],  kr[1],  kr[2],  kr[3]);
        *reinterpret_cast<float4*>(dst + 4)  = make_float4(kr[4],  kr[5],  kr[6],  kr[7]);
        *reinterpret_cast<float4*>(dst + 8)  = make_float4(kr[8],  kr[9],  kr[10], kr[11]);
        *reinterpret_cast<float4*>(dst + 12) = make_float4(kr[12], kr[13], kr[14], kr[15]);
    }
}

// ---------------- kernel spectrum ----------------
__global__ void __launch_bounds__(512, 3) kf_kernel() {
    extern __shared__ float2 S[];
    int d = blockIdx.x;
    int tid = threadIdx.x;
    const float2* krow = (const float2*)(g_kT + (size_t)d * SEQ_LEN);
    fwd_pass1_fused(S, tid, krow);
    __syncthreads();
    fwd_group3<3>(S, tid); __syncthreads();
    fwd_group3<6>(S, tid); __syncthreads();
    fwd_group16(S, tid);   __syncthreads();

    const float invM = 1.0f / 16384.0f;
    float2* Kf = g_Kf + (size_t)d * (NFFT + 1);
    if (tid == 0) {
        float2 c0 = S[PHYS(0)];
        Kf[0]    = make_float2((c0.x + c0.y) * invM, 0.f);
        Kf[NFFT] = make_float2((c0.x - c0.y) * invM, 0.f);
    }
    for (int t = tid; t < 4096; t += 512) {
        int k  = t + 1;
        int p1 = __brev(k) >> 19;
        int p2 = __brev(8192 - k) >> 19;
        float2 C1 = S[PHYS(p1)], C2 = S[PHYS(p2)];
        float Ex = 0.5f * (C1.x + C2.x), Ey = 0.5f * (C1.y - C2.y);
        float Dx = C1.x - C2.x,          Dy = C1.y + C2.y;
        float Ox = 0.5f * Dy,            Oy = -0.5f * Dx;
        float2 w = g_tw[k];
        float wOx = Ox * w.x - Oy * w.y, wOy = Ox * w.y + Oy * w.x;
        Kf[k]        = make_float2((Ex + wOx) * invM, (Ey + wOy) * invM);
        Kf[8192 - k] = make_float2((Ex - wOx) * invM, -(Ey - wOy) * invM);
    }
}

// ---------------- fused conv: reads x and writes out directly (d-major grid) ----
__global__ void __launch_bounds__(512, 3) conv_kernel(const float* __restrict__ x,
                                                      float* __restrict__ out,
                                                      const float* __restrict__ bias) {
    extern __shared__ float2 S[];
    int col = blockIdx.x;           // d*8 + b  (d-major: Kf + x-sector L2 reuse)
    int d   = col >> 3;
    int b   = col & 7;
    int tid = threadIdx.x;

    const float* xg = x + (size_t)b * SEQ_LEN * HIDDEN + d;
    fwd_pass1_direct(S, tid, xg);
    __syncthreads();
    fwd_group3<3>(S, tid); __syncthreads();
    fwd_group3<6>(S, tid); __syncthreads();
    fwd_group16(S, tid);   __syncthreads();

    const float2* Kf = g_Kf + (size_t)d * (NFFT + 1);
    if (tid == 0) {
        float2 c0 = S[PHYS(0)];
        float U0 = c0.x + c0.y, UN = c0.x - c0.y;
        float2 F0 = Kf[0], FN = Kf[NFFT];
        float2 Y0 = make_float2(U0 * F0.x, U0 * F0.y);
        float2 YN = make_float2(UN * FN.x, UN * FN.y);
        float Eyx = 0.5f * (Y0.x + YN.x), Eyy = 0.5f * (Y0.y + YN.y);
        float Dyx = 0.5f * (Y0.x - YN.x), Dyy = 0.5f * (Y0.y - YN.y);
        S[PHYS(0)] = make_float2(Eyx - Dyy, Eyy + Dyx);
    }
    for (int t = tid; t < 4096; t += 512) {
        int k  = t + 1;
        int k2 = 8192 - k;
        int p1 = __brev(k)  >> 19;
        int p2 = __brev(k2) >> 19;
        int q1 = PHYS(p1), q2 = PHYS(p2);
        float2 C1 = S[q1], C2 = S[q2];
        float Ex = 0.5f * (C1.x + C2.x), Ey = 0.5f * (C1.y - C2.y);
        float Dx = C1.x - C2.x,          Dy = C1.y + C2.y;
        float Ox = 0.5f * Dy,            Oy = -0.5f * Dx;
        float2 w = g_tw[k];
        float wOx = Ox * w.x - Oy * w.y, wOy = Ox * w.y + Oy * w.x;
        float2 Uk  = make_float2(Ex + wOx, Ey + wOy);
        float2 UkN = make_float2(Ex - wOx, Ey - wOy);
        float2 F1 = Kf[k];
        float2 F2 = Kf[k2];
        float2 Y1 = cmul(Uk, F1);
        float2 Y2 = cmul(UkN, make_float2(F2.x, -F2.y));
        float2 Eyc = make_float2(0.5f * (Y1.x + Y2.x), 0.5f * (Y1.y + Y2.y));
        float2 Dyc = make_float2(0.5f * (Y1.x - Y2.x), 0.5f * (Y1.y - Y2.y));
        float2 Oyc = make_float2(Dyc.x * w.x + Dyc.y * w.y, Dyc.y * w.x - Dyc.x * w.y);
        float2 Zk  = make_float2(Eyc.x - Oyc.y, Eyc.y + Oyc.x);
        // mirror bin: w2 = g_tw[8192-k] = (-w.x, w.y)
        float2 Y1p = cmul(make_float2(UkN.x, -UkN.y), F2);
        float2 Y2p = cmul(make_float2(Uk.x, -Uk.y), make_float2(F1.x, -F1.y));
        float2 w2  = make_float2(-w.x, w.y);
        float2 Eyp = make_float2(0.5f * (Y1p.x + Y2p.x), 0.5f * (Y1p.y + Y2p.y));
        float2 Dyp = make_float2(0.5f * (Y1p.x - Y2p.x), 0.5f * (Y1p.y - Y2p.y));
        float2 Oyp = make_float2(Dyp.x * w2.x + Dyp.y * w2.y, Dyp.y * w2.x - Dyp.x * w2.y);
        float2 Zk2 = make_float2(Eyp.x - Oyp.y, Eyp.y + Oyp.x);
        S[q1] = Zk;
        S[q2] = Zk2;
    }
    __syncthreads();

    inv_group16(S, tid);   __syncthreads();
    inv_group3<4>(S, tid); __syncthreads();
    inv_group3<7>(S, tid); __syncthreads();

    const float invN = 1.0f / 8192.0f;
    float bv = bias[d];
    float* og = out + (size_t)b * SEQ_LEN * HIDDEN + d;
    inv_final_direct(S, tid, og, invN, bv);
}

// ---------------- launch ----------------
extern "C" void kernel_launch(void* const* d_in, const int* in_sizes, int n_in,
                              void* d_out, int out_size) {
    const float* x       = (const float*)d_in[0];
    const float* w_in    = (const float*)d_in[1];
    const float* b_in    = (const float*)d_in[2];
    const float* freq_in = (const float*)d_in[3];
    const float* w_h0    = (const float*)d_in[4];
    const float* b_h0    = (const float*)d_in[5];
    const float* freq_h0 = (const float*)d_in[6];
    const float* w_h1    = (const float*)d_in[7];
    const float* b_h1    = (const float*)d_in[8];
    const float* freq_h1 = (const float*)d_in[9];
    const float* w_out   = (const float*)d_in[10];
    const float* bias    = (const float*)d_in[11];
    float* out = (float*)d_out;

    const int FILTER_SMEM = (2048 + 768 * 17) * 4;   // 60416 B

    cudaFuncSetAttribute(kf_kernel,     cudaFuncAttributeMaxDynamicSharedMemorySize, SMEM_BYTES);
    cudaFuncSetAttribute(conv_kernel,   cudaFuncAttributeMaxDynamicSharedMemorySize, SMEM_BYTES);
    cudaFuncSetAttribute(filter_kernel, cudaFuncAttributeMaxDynamicSharedMemorySize, FILTER_SMEM);

    twiddle_init<<<16, 512>>>();
    filter_kernel<<<SEQ_LEN / 16, 256, FILTER_SMEM>>>(w_in, b_in, freq_in, w_h0, b_h0, freq_h0,
                                                      w_h1, b_h1, freq_h1, w_out);
    kf_kernel<<<HIDDEN, 512, SMEM_BYTES>>>();
    conv_kernel<<<BATCH * HIDDEN, 512, SMEM_BYTES>>>(x, out, bias);
}

// round 13
// speedup vs baseline: 1.5005x; 1.5005x over previous
#include <cuda_runtime.h>
#include <math.h>

#define SEQ_LEN 8192
#define HIDDEN  768
#define BATCH   8
#define NFFT    8192     // packed complex FFT size
#define MFFT    16384    // real FFT size
#define SMEM_BYTES (NFFT * 8)   // 65536

// ---------------- static scratch (allocation-free rule) ----------------
__device__ float2 g_tw[NFFT];                         // exp(-2*pi*i*k/16384)
__device__ float  g_kT[HIDDEN * SEQ_LEN];             // filter transposed (D, L)
__device__ float2 g_Kf[HIDDEN * (NFFT + 1)];          // rfft(k)/16384 per d
__device__ float  g_xT[(size_t)BATCH * HIDDEN * SEQ_LEN];  // x transposed (B*D, L)
__device__ float  g_yT[(size_t)BATCH * HIDDEN * SEQ_LEN];  // y transposed (B*D, L)

__device__ __forceinline__ float2 cmul(float2 a, float2 b) {
    return make_float2(a.x * b.x - a.y * b.y, a.x * b.y + a.y * b.x);
}
__device__ __forceinline__ float2 cmulc(float2 a, float2 b) {   // a * conj(b)
    return make_float2(a.x * b.x + a.y * b.y, a.y * b.x - a.x * b.y);
}
__device__ __forceinline__ float2 csq(float2 a) {
    return make_float2(a.x * a.x - a.y * a.y, 2.0f * a.x * a.y);
}
__device__ __forceinline__ float2 mulni(float2 a) {  // a * (-i)
    return make_float2(a.y, -a.x);
}
// XOR-swizzled physical index: conflict-free for strided FFT passes and
// 2-way worst case for the bit-reversed pointwise pass.
__device__ __forceinline__ int PHYS(int i) {
    return (i & ~15) | ((i ^ (i >> 4) ^ (i >> 8)) & 15);
}

#define FBF(a, b, w) { float2 u_=(a), v_=(b); (a)=make_float2(u_.x+v_.x,u_.y+v_.y); \
                       float2 d_=make_float2(u_.x-v_.x,u_.y-v_.y); (b)=cmul(d_, (w)); }
#define FBF1(a, b)   { float2 u_=(a), v_=(b); (a)=make_float2(u_.x+v_.x,u_.y+v_.y); \
                       (b)=make_float2(u_.x-v_.x,u_.y-v_.y); }
#define FBFNI(a, b)  { float2 u_=(a), v_=(b); (a)=make_float2(u_.x+v_.x,u_.y+v_.y); \
                       (b)=make_float2(u_.y-v_.y, -(u_.x-v_.x)); }
#define IBF(a, b, w) { float2 u_=(a); float2 tv_=cmulc((b),(w)); \
                       (a)=make_float2(u_.x+tv_.x,u_.y+tv_.y); (b)=make_float2(u_.x-tv_.x,u_.y-tv_.y); }
#define IBF1(a, b)   FBF1(a, b)
#define IBFPI(a, b)  { float2 u_=(a), v_=(b); float2 tv_=make_float2(-v_.y, v_.x); \
                       (a)=make_float2(u_.x+tv_.x,u_.y+tv_.y); (b)=make_float2(u_.x-tv_.x,u_.y-tv_.y); }

#define C8f 0.70710678118654752f
#define CAf 0.92387953251128676f
#define CBf 0.38268343236508977f

// ---------------- twiddle init ----------------
__global__ void twiddle_init() {
    int k = blockIdx.x * blockDim.x + threadIdx.x;
    if (k < NFFT) {
        double a = -2.0 * M_PI * (double)k / (double)MFFT;
        g_tw[k] = make_float2((float)cos(a), (float)sin(a));
    }
}

// ---------------- fused forward pass 1 (stages 0,1,2): global load + zero pad ----
__device__ __forceinline__ void fwd_pass1_fused(float2* S, int tid, const float2* __restrict__ g) {
#pragma unroll
    for (int it = 0; it < 2; it++) {
        int t = tid + it * 512;           // base = t, r = t
        float2 x[8];
#pragma unroll
        for (int e = 0; e < 4; e++) x[e] = g[t + e * 1024];
        float2 w1 = g_tw[t << 1];
        float2 w2 = csq(w1);
        float2 w4 = csq(w2);
        // stage 0 with zero upper half
        {
            float2 wr1 = cmul(w1, make_float2(C8f, -C8f));
            float2 wr2 = mulni(w1);
            float2 wr3 = cmul(w1, make_float2(-C8f, -C8f));
            x[4] = cmul(x[0], w1);
            x[5] = cmul(x[1], wr1);
            x[6] = cmul(x[2], wr2);
            x[7] = cmul(x[3], wr3);
        }
        // stage 1
        {
            float2 w2n = mulni(w2);
            FBF(x[0], x[2], w2);
            FBF(x[1], x[3], w2n);
            FBF(x[4], x[6], w2);
            FBF(x[5], x[7], w2n);
        }
        // stage 2
        FBF(x[0], x[1], w4);
        FBF(x[2], x[3], w4);
        FBF(x[4], x[5], w4);
        FBF(x[6], x[7], w4);
#pragma unroll
        for (int e = 0; e < 8; e++) S[PHYS(t + e * 1024)] = x[e];
    }
}

// ---------------- grouped forward stages s, s+1, s+2 (s in {3,6}) ----------------
template<int s>
__device__ __forceinline__ void fwd_group3(float2* S, int tid) {
    const int h = 1 << (10 - s);
#pragma unroll
    for (int it = 0; it < 2; it++) {
        int t = tid + it * 512;
        int r = t & (h - 1);
        int base = ((t >> (10 - s)) << (13 - s)) | r;
        float2 x[8];
#pragma unroll
        for (int e = 0; e < 8; e++) x[e] = S[PHYS(base + e * h)];
        float2 w1 = g_tw[r << (s + 1)];
        float2 w2 = csq(w1);
        float2 w4 = csq(w2);
        {
            float2 wr1 = cmul(w1, make_float2(C8f, -C8f));
            float2 wr2 = mulni(w1);
            float2 wr3 = cmul(w1, make_float2(-C8f, -C8f));
            FBF(x[0], x[4], w1);
            FBF(x[1], x[5], wr1);
            FBF(x[2], x[6], wr2);
            FBF(x[3], x[7], wr3);
        }
        {
            float2 w2n = mulni(w2);
            FBF(x[0], x[2], w2);
            FBF(x[1], x[3], w2n);
            FBF(x[4], x[6], w2);
            FBF(x[5], x[7], w2n);
        }
        FBF(x[0], x[1], w4);
        FBF(x[2], x[3], w4);
        FBF(x[4], x[5], w4);
        FBF(x[6], x[7], w4);
#pragma unroll
        for (int e = 0; e < 8; e++) S[PHYS(base + e * h)] = x[e];
    }
}

// ---------------- forward stages 9..12 on 16 consecutive elements ----------------
__device__ __forceinline__ void fwd_group16(float2* S, int tid) {
    float2* row = S + tid * 16;
    int hh = (tid ^ (tid >> 4)) & 15;        // PHYS(16*tid + e) = 16*tid + (e ^ hh)
    float2 x[16];
#pragma unroll
    for (int e = 0; e < 16; e++) x[e] = row[e ^ hh];
    FBF1 (x[0], x[8]);
    FBF  (x[1], x[9],  make_float2( CAf, -CBf));
    FBF  (x[2], x[10], make_float2( C8f, -C8f));
    FBF  (x[3], x[11], make_float2( CBf, -CAf));
    FBFNI(x[4], x[12]);
    FBF  (x[5], x[13], make_float2(-CBf, -CAf));
    FBF  (x[6], x[14], make_float2(-C8f, -C8f));
    FBF  (x[7], x[15], make_float2(-CAf, -CBf));
#pragma unroll
    for (int g = 0; g < 16; g += 8) {
        FBF1 (x[g+0], x[g+4]);
        FBF  (x[g+1], x[g+5], make_float2( C8f, -C8f));
        FBFNI(x[g+2], x[g+6]);
        FBF  (x[g+3], x[g+7], make_float2(-C8f, -C8f));
    }
#pragma unroll
    for (int g = 0; g < 16; g += 4) {
        FBF1 (x[g+0], x[g+2]);
        FBFNI(x[g+1], x[g+3]);
    }
#pragma unroll
    for (int g = 0; g < 16; g += 2) FBF1(x[g], x[g+1]);
#pragma unroll
    for (int e = 0; e < 16; e++) row[e ^ hh] = x[e];
}

// ---------------- inverse stages 0..3 on 16 consecutive elements ----------------
__device__ __forceinline__ void inv_group16(float2* S, int tid) {
    float2* row = S + tid * 16;
    int hh = (tid ^ (tid >> 4)) & 15;
    float2 x[16];
#pragma unroll
    for (int e = 0; e < 16; e++) x[e] = row[e ^ hh];
#pragma unroll
    for (int g = 0; g < 16; g += 2) IBF1(x[g], x[g+1]);
#pragma unroll
    for (int g = 0; g < 16; g += 4) {
        IBF1 (x[g+0], x[g+2]);
        IBFPI(x[g+1], x[g+3]);
    }
#pragma unroll
    for (int g = 0; g < 16; g += 8) {
        IBF1 (x[g+0], x[g+4]);
        IBF  (x[g+1], x[g+5], make_float2( C8f, -C8f));
        IBFPI(x[g+2], x[g+6]);
        IBF  (x[g+3], x[g+7], make_float2(-C8f, -C8f));
    }
    IBF1 (x[0], x[8]);
    IBF  (x[1], x[9],  make_float2( CAf, -CBf));
    IBF  (x[2], x[10], make_float2( C8f, -C8f));
    IBF  (x[3], x[11], make_float2( CBf, -CAf));
    IBFPI(x[4], x[12]);
    IBF  (x[5], x[13], make_float2(-CBf, -CAf));
    IBF  (x[6], x[14], make_float2(-C8f, -C8f));
    IBF  (x[7], x[15], make_float2(-CAf, -CBf));
#pragma unroll
    for (int e = 0; e < 16; e++) row[e ^ hh] = x[e];
}

// ---------------- grouped inverse stages s0, s0+1, s0+2 (s0 in {4,7}) -------
template<int s0>
__device__ __forceinline__ void inv_group3(float2* S, int tid) {
    const int h = 1 << s0;
#pragma unroll
    for (int it = 0; it < 2; it++) {
        int t = tid + it * 512;
        int r = t & (h - 1);
        int base = ((t >> s0) << (s0 + 3)) | r;
        float2 x[8];
#pragma unroll
        for (int e = 0; e < 8; e++) x[e] = S[PHYS(base + e * h)];
        float2 wB = g_tw[r << (11 - s0)];
        float2 wB2 = csq(wB);
        float2 wB4 = csq(wB2);
        IBF(x[0], x[1], wB4);
        IBF(x[2], x[3], wB4);
        IBF(x[4], x[5], wB4);
        IBF(x[6], x[7], wB4);
        {
            float2 w2n = mulni(wB2);
            IBF(x[0], x[2], wB2);
            IBF(x[1], x[3], w2n);
            IBF(x[4], x[6], wB2);
            IBF(x[5], x[7], w2n);
        }
        {
            float2 wr1 = cmul(wB, make_float2(C8f, -C8f));
            float2 wr2 = mulni(wB);
            float2 wr3 = cmul(wB, make_float2(-C8f, -C8f));
            IBF(x[0], x[4], wB);
            IBF(x[1], x[5], wr1);
            IBF(x[2], x[6], wr2);
            IBF(x[3], x[7], wr3);
        }
#pragma unroll
        for (int e = 0; e < 8; e++) S[PHYS(base + e * h)] = x[e];
    }
}

// ---------------- fused inverse final pass (stages 10,11,12) --------------------
__device__ __forceinline__ void inv_pass4_fused(float2* S, int tid,
                                                float2* __restrict__ gdst,
                                                float scale, float bv) {
#pragma unroll
    for (int it = 0; it < 2; it++) {
        int t = tid + it * 512;           // base = t, r = t (s0 = 10)
        float2 x[8];
#pragma unroll
        for (int e = 0; e < 8; e++) x[e] = S[PHYS(t + e * 1024)];
        float2 wB = g_tw[t << 1];
        float2 wB2 = csq(wB);
        float2 wB4 = csq(wB2);
        IBF(x[0], x[1], wB4);
        IBF(x[2], x[3], wB4);
        IBF(x[4], x[5], wB4);
        IBF(x[6], x[7], wB4);
        {
            float2 w2n = mulni(wB2);
            IBF(x[0], x[2], wB2);
            IBF(x[1], x[3], w2n);
            IBF(x[4], x[6], wB2);
            IBF(x[5], x[7], w2n);
        }
        {
            float2 wr1 = cmul(wB, make_float2(C8f, -C8f));
            float2 wr2 = mulni(wB);
            float2 wr3 = cmul(wB, make_float2(-C8f, -C8f));
            float2 t0 = cmulc(x[4], wB);
            float2 t1 = cmulc(x[5], wr1);
            float2 t2 = cmulc(x[6], wr2);
            float2 t3 = cmulc(x[7], wr3);
            x[0] = make_float2(x[0].x + t0.x, x[0].y + t0.y);
            x[1] = make_float2(x[1].x + t1.x, x[1].y + t1.y);
            x[2] = make_float2(x[2].x + t2.x, x[2].y + t2.y);
            x[3] = make_float2(x[3].x + t3.x, x[3].y + t3.y);
        }
#pragma unroll
        for (int e = 0; e < 4; e++)
            gdst[t + e * 1024] = make_float2(x[e].x * scale + bv, x[e].y * scale + bv);
    }
}

// ---------------- implicit filter MLP + modulation, writes g_kT directly --------
// Dynamic smem: hA[16][64], hB[16][64], ktile[768][17]
__global__ void filter_kernel(
    const float* __restrict__ w_in,  const float* __restrict__ b_in,  const float* __restrict__ freq_in,
    const float* __restrict__ w_h0,  const float* __restrict__ b_h0,  const float* __restrict__ freq_h0,
    const float* __restrict__ w_h1,  const float* __restrict__ b_h1,  const float* __restrict__ freq_h1,
    const float* __restrict__ w_out)
{
    extern __shared__ float sm[];
    float* hA    = sm;              // 16*64
    float* hB    = sm + 1024;       // 16*64
    float* ktile = sm + 2048;       // 768*17
    int l0 = blockIdx.x * 16;
    int tid = threadIdx.x;

    for (int idx = tid; idx < 16 * 64; idx += 256) {
        int ll = idx >> 6, j = idx & 63;
        int l = l0 + ll;
        float t0 = (float)l / (float)(SEQ_LEN - 1);
        float ang = (float)(2.0 * M_PI * 1e-4 / (double)SEQ_LEN) * (float)l;
        float z1 = cosf(ang), z2 = -sinf(ang);
        float v = t0 * w_in[j] + z1 * w_in[64 + j] + z2 * w_in[128 + j] + b_in[j];
        hA[ll * 64 + j] = sinf(freq_in[j] * v);
    }
    __syncthreads();
    for (int idx = tid; idx < 16 * 64; idx += 256) {
        int ll = idx >> 6, j = idx & 63;
        float acc = b_h0[j];
#pragma unroll
        for (int i = 0; i < 64; i++) acc += hA[ll * 64 + i] * w_h0[i * 64 + j];
        hB[ll * 64 + j] = sinf(freq_h0[j] * acc);
    }
    __syncthreads();
    for (int idx = tid; idx < 16 * 64; idx += 256) {
        int ll = idx >> 6, j = idx & 63;
        float acc = b_h1[j];
#pragma unroll
        for (int i = 0; i < 64; i++) acc += hB[ll * 64 + i] * w_h1[i * 64 + j];
        hA[ll * 64 + j] = sinf(freq_h1[j] * acc);
    }
    __syncthreads();

    const float MIND = 3.0701134573253943f;
    const float MAXD = 15.350567286626972f;
    for (int ll = 0; ll < 16; ll++) {
        int l = l0 + ll;
        float t0 = (float)l / (float)(SEQ_LEN - 1);
        for (int d = tid; d < HIDDEN; d += 256) {
            float acc = 0.f;
#pragma unroll
            for (int i = 0; i < 64; i++) acc += hA[ll * 64 + i] * w_out[i * HIDDEN + d];
            float ad = MIND + (MAXD - MIND) * ((float)d / 767.0f);
            ktile[d * 17 + ll] = acc * expf(-t0 * ad);
        }
    }
    __syncthreads();

    // write 768 rows of 16 floats each (64 B contiguous per row) as 4x float4
#pragma unroll
    for (int j = 0; j < 3; j++) {
        int row = j * 256 + tid;
        const float* kr = ktile + row * 17;
        float* dst = g_kT + (size_t)row * SEQ_LEN + l0;
        *reinterpret_cast<float4*>(dst)      = make_float4(kr[0],  kr[1],  kr[2],  kr[3]);
        *reinterpret_cast<float4*>(dst + 4)  = make_float4(kr[4],  kr[5],  kr[6],  kr[7]);
        *reinterpret_cast<float4*>(dst + 8)  = make_float4(kr[8],  kr[9],  kr[10], kr[11]);
        *reinterpret_cast<float4*>(dst + 12) = make_float4(kr[12], kr[13], kr[14], kr[15]);
    }
}

// ---------------- transposes: 128(l) x 32(d) per block, float2 on L side --------
__global__ void transpose_in(const float* __restrict__ x) {
    __shared__ float tile[128][33];
    int b = blockIdx.z;
    int l0 = blockIdx.x * 128, d0 = blockIdx.y * 32;
    int tx = threadIdx.x, ty = threadIdx.y;   // (32, 8)
    const float* xb = x + (size_t)b * SEQ_LEN * HIDDEN;
#pragma unroll
    for (int j = 0; j < 16; j++) {
        int ll = j * 8 + ty;
        tile[ll][tx] = xb[(size_t)(l0 + ll) * HIDDEN + d0 + tx];
    }
    __syncthreads();
    float* dst = g_xT + (size_t)(b * HIDDEN + d0) * SEQ_LEN;
    int tid = ty * 32 + tx;
#pragma unroll
    for (int j = 0; j < 8; j++) {
        int idx = j * 256 + tid;   // 0..2047
        int dr = idx >> 6;         // 0..31
        int l2 = idx & 63;         // 0..63
        float2 v = make_float2(tile[2 * l2][dr], tile[2 * l2 + 1][dr]);
        *reinterpret_cast<float2*>(&dst[(size_t)dr * SEQ_LEN + l0 + 2 * l2]) = v;
    }
}

__global__ void transpose_out(float* __restrict__ out) {
    __shared__ float tile[128][33];
    int b = blockIdx.z;
    int l0 = blockIdx.x * 128, d0 = blockIdx.y * 32;
    int tx = threadIdx.x, ty = threadIdx.y;
    const float* src = g_yT + (size_t)(b * HIDDEN + d0) * SEQ_LEN;
    int tid = ty * 32 + tx;
#pragma unroll
    for (int j = 0; j < 8; j++) {
        int idx = j * 256 + tid;
        int dr = idx >> 6;
        int l2 = idx & 63;
        float2 v = *reinterpret_cast<const float2*>(&src[(size_t)dr * SEQ_LEN + l0 + 2 * l2]);
        tile[2 * l2][dr]     = v.x;
        tile[2 * l2 + 1][dr] = v.y;
    }
    __syncthreads();
    float* ob = out + (size_t)b * SEQ_LEN * HIDDEN;
#pragma unroll
    for (int j = 0; j < 16; j++) {
        int ll = j * 8 + ty;
        ob[(size_t)(l0 + ll) * HIDDEN + d0 + tx] = tile[ll][tx];
    }
}

// ---------------- kernel spectrum ----------------
__global__ void __launch_bounds__(512, 3) kf_kernel() {
    extern __shared__ float2 S[];
    int d = blockIdx.x;
    int tid = threadIdx.x;
    const float2* krow = (const float2*)(g_kT + (size_t)d * SEQ_LEN);
    fwd_pass1_fused(S, tid, krow);
    __syncthreads();
    fwd_group3<3>(S, tid); __syncthreads();
    fwd_group3<6>(S, tid); __syncthreads();
    fwd_group16(S, tid);   __syncthreads();

    const float invM = 1.0f / 16384.0f;
    float2* Kf = g_Kf + (size_t)d * (NFFT + 1);
    if (tid == 0) {
        float2 c0 = S[PHYS(0)];
        Kf[0]    = make_float2((c0.x + c0.y) * invM, 0.f);
        Kf[NFFT] = make_float2((c0.x - c0.y) * invM, 0.f);
    }
    for (int t = tid; t < 4096; t += 512) {
        int k  = t + 1;
        int p1 = __brev(k) >> 19;
        int p2 = __brev(8192 - k) >> 19;
        float2 C1 = S[PHYS(p1)], C2 = S[PHYS(p2)];
        float Ex = 0.5f * (C1.x + C2.x), Ey = 0.5f * (C1.y - C2.y);
        float Dx = C1.x - C2.x,          Dy = C1.y + C2.y;
        float Ox = 0.5f * Dy,            Oy = -0.5f * Dx;
        float2 w = g_tw[k];
        float wOx = Ox * w.x - Oy * w.y, wOy = Ox * w.y + Oy * w.x;
        Kf[k]        = make_float2((Ex + wOx) * invM, (Ey + wOy) * invM);
        Kf[8192 - k] = make_float2((Ex - wOx) * invM, -(Ey - wOy) * invM);
    }
}

// ---------------- fused conv (d-major grid for Kf L2 reuse) ----------------
__global__ void __launch_bounds__(512, 3) conv_kernel(const float* __restrict__ bias) {
    extern __shared__ float2 S[];
    int bid = blockIdx.x;           // d*8 + b : 8 adjacent blocks share one Kf row
    int d   = bid >> 3;
    int b   = bid & 7;
    int col = b * HIDDEN + d;       // g_xT / g_yT row index
    int tid = threadIdx.x;

    const float2* row = (const float2*)(g_xT + (size_t)col * SEQ_LEN);
    fwd_pass1_fused(S, tid, row);
    __syncthreads();
    fwd_group3<3>(S, tid); __syncthreads();
    fwd_group3<6>(S, tid); __syncthreads();
    fwd_group16(S, tid);   __syncthreads();

    const float2* Kf = g_Kf + (size_t)d * (NFFT + 1);
    if (tid == 0) {
        float2 c0 = S[PHYS(0)];
        float U0 = c0.x + c0.y, UN = c0.x - c0.y;
        float2 F0 = Kf[0], FN = Kf[NFFT];
        float2 Y0 = make_float2(U0 * F0.x, U0 * F0.y);
        float2 YN = make_float2(UN * FN.x, UN * FN.y);
        float Eyx = 0.5f * (Y0.x + YN.x), Eyy = 0.5f * (Y0.y + YN.y);
        float Dyx = 0.5f * (Y0.x - YN.x), Dyy = 0.5f * (Y0.y - YN.y);
        S[PHYS(0)] = make_float2(Eyx - Dyy, Eyy + Dyx);
    }
    for (int t = tid; t < 4096; t += 512) {
        int k  = t + 1;
        int k2 = 8192 - k;
        int p1 = __brev(k)  >> 19;
        int p2 = __brev(k2) >> 19;
        int q1 = PHYS(p1), q2 = PHYS(p2);
        float2 C1 = S[q1], C2 = S[q2];
        float Ex = 0.5f * (C1.x + C2.x), Ey = 0.5f * (C1.y - C2.y);
        float Dx = C1.x - C2.x,          Dy = C1.y + C2.y;
        float Ox = 0.5f * Dy,            Oy = -0.5f * Dx;
        float2 w = g_tw[k];
        float wOx = Ox * w.x - Oy * w.y, wOy = Ox * w.y + Oy * w.x;
        float2 Uk  = make_float2(Ex + wOx, Ey + wOy);
        float2 UkN = make_float2(Ex - wOx, Ey - wOy);
        float2 F1 = Kf[k];
        float2 F2 = Kf[k2];
        float2 Y1 = cmul(Uk, F1);
        float2 Y2 = cmul(UkN, make_float2(F2.x, -F2.y));
        float2 Eyc = make_float2(0.5f * (Y1.x + Y2.x), 0.5f * (Y1.y + Y2.y));
        float2 Dyc = make_float2(0.5f * (Y1.x - Y2.x), 0.5f * (Y1.y - Y2.y));
        float2 Oyc = make_float2(Dyc.x * w.x + Dyc.y * w.y, Dyc.y * w.x - Dyc.x * w.y);
        float2 Zk  = make_float2(Eyc.x - Oyc.y, Eyc.y + Oyc.x);
        // mirror bin: w2 = g_tw[8192-k] = (-w.x, w.y)
        float2 Y1p = cmul(make_float2(UkN.x, -UkN.y), F2);
        float2 Y2p = cmul(make_float2(Uk.x, -Uk.y), make_float2(F1.x, -F1.y));
        float2 w2  = make_float2(-w.x, w.y);
        float2 Eyp = make_float2(0.5f * (Y1p.x + Y2p.x), 0.5f * (Y1p.y + Y2p.y));
        float2 Dyp = make_float2(0.5f * (Y1p.x - Y2p.x), 0.5f * (Y1p.y - Y2p.y));
        float2 Oyp = make_float2(Dyp.x * w2.x + Dyp.y * w2.y, Dyp.y * w2.x - Dyp.x * w2.y);
        float2 Zk2 = make_float2(Eyp.x - Oyp.y, Eyp.y + Oyp.x);
        S[q1] = Zk;
        S[q2] = Zk2;
    }
    __syncthreads();

    inv_group16(S, tid);   __syncthreads();
    inv_group3<4>(S, tid); __syncthreads();
    inv_group3<7>(S, tid); __syncthreads();

    const float invN = 1.0f / 8192.0f;
    float bv = bias[d];
    float2* orow = (float2*)(g_yT + (size_t)col * SEQ_LEN);
    inv_pass4_fused(S, tid, orow, invN, bv);
}

// ---------------- launch ----------------
extern "C" void kernel_launch(void* const* d_in, const int* in_sizes, int n_in,
                              void* d_out, int out_size) {
    const float* x       = (const float*)d_in[0];
    const float* w_in    = (const float*)d_in[1];
    const float* b_in    = (const float*)d_in[2];
    const float* freq_in = (const float*)d_in[3];
    const float* w_h0    = (const float*)d_in[4];
    const float* b_h0    = (const float*)d_in[5];
    const float* freq_h0 = (const float*)d_in[6];
    const float* w_h1    = (const float*)d_in[7];
    const float* b_h1    = (const float*)d_in[8];
    const float* freq_h1 = (const float*)d_in[9];
    const float* w_out   = (const float*)d_in[10];
    const float* bias    = (const float*)d_in[11];
    float* out = (float*)d_out;

    const int FILTER_SMEM = (2048 + 768 * 17) * 4;   // 60416 B

    cudaFuncSetAttribute(kf_kernel,     cudaFuncAttributeMaxDynamicSharedMemorySize, SMEM_BYTES);
    cudaFuncSetAttribute(conv_kernel,   cudaFuncAttributeMaxDynamicSharedMemorySize, SMEM_BYTES);
    cudaFuncSetAttribute(filter_kernel, cudaFuncAttributeMaxDynamicSharedMemorySize, FILTER_SMEM);

    twiddle_init<<<16, 512>>>();
    filter_kernel<<<SEQ_LEN / 16, 256, FILTER_SMEM>>>(w_in, b_in, freq_in, w_h0, b_h0, freq_h0,
                                                      w_h1, b_h1, freq_h1, w_out);
    dim3 tblk(32, 8);
    dim3 tgrid(SEQ_LEN / 128, HIDDEN / 32, BATCH);
    transpose_in<<<tgrid, tblk>>>(x);
    kf_kernel<<<HIDDEN, 512, SMEM_BYTES>>>();
    conv_kernel<<<BATCH * HIDDEN, 512, SMEM_BYTES>>>(bias);
    transpose_out<<<tgrid, tblk>>>(out);
}

// round 14
// speedup vs baseline: 1.5433x; 1.0285x over previous
#include <cuda_runtime.h>
#include <math.h>

#define SEQ_LEN 8192
#define HIDDEN  768
#define BATCH   8
#define NFFT    8192     // packed complex FFT size
#define MFFT    16384    // real FFT size
#define SMEM_BYTES (NFFT * 8)   // 65536

// ---------------- static scratch (allocation-free rule) ----------------
__device__ float2 g_tw[NFFT];                         // exp(-2*pi*i*k/16384)
__device__ float  g_kT[HIDDEN * SEQ_LEN];             // filter transposed (D, L)
__device__ float2 g_Kf[HIDDEN * (NFFT + 1)];          // rfft(k)/16384 per d
__device__ float  g_xT[(size_t)BATCH * HIDDEN * SEQ_LEN];  // x transposed (B*D, L)
__device__ float  g_yT[(size_t)BATCH * HIDDEN * SEQ_LEN];  // y transposed (B*D, L)

__device__ __forceinline__ float2 cmul(float2 a, float2 b) {
    return make_float2(a.x * b.x - a.y * b.y, a.x * b.y + a.y * b.x);
}
__device__ __forceinline__ float2 cmulc(float2 a, float2 b) {   // a * conj(b)
    return make_float2(a.x * b.x + a.y * b.y, a.y * b.x - a.x * b.y);
}
__device__ __forceinline__ float2 csq(float2 a) {
    return make_float2(a.x * a.x - a.y * a.y, 2.0f * a.x * a.y);
}
__device__ __forceinline__ float2 mulni(float2 a) {  // a * (-i)
    return make_float2(a.y, -a.x);
}
// XOR-swizzled physical index: conflict-free for strided FFT passes and
// 2-way worst case for the bit-reversed pointwise pass.
__device__ __forceinline__ int PHYS(int i) {
    return (i & ~15) | ((i ^ (i >> 4) ^ (i >> 8)) & 15);
}

#define FBF(a, b, w) { float2 u_=(a), v_=(b); (a)=make_float2(u_.x+v_.x,u_.y+v_.y); \
                       float2 d_=make_float2(u_.x-v_.x,u_.y-v_.y); (b)=cmul(d_, (w)); }
#define FBF1(a, b)   { float2 u_=(a), v_=(b); (a)=make_float2(u_.x+v_.x,u_.y+v_.y); \
                       (b)=make_float2(u_.x-v_.x,u_.y-v_.y); }
#define FBFNI(a, b)  { float2 u_=(a), v_=(b); (a)=make_float2(u_.x+v_.x,u_.y+v_.y); \
                       (b)=make_float2(u_.y-v_.y, -(u_.x-v_.x)); }
#define IBF(a, b, w) { float2 u_=(a); float2 tv_=cmulc((b),(w)); \
                       (a)=make_float2(u_.x+tv_.x,u_.y+tv_.y); (b)=make_float2(u_.x-tv_.x,u_.y-tv_.y); }
#define IBF1(a, b)   FBF1(a, b)
#define IBFPI(a, b)  { float2 u_=(a), v_=(b); float2 tv_=make_float2(-v_.y, v_.x); \
                       (a)=make_float2(u_.x+tv_.x,u_.y+tv_.y); (b)=make_float2(u_.x-tv_.x,u_.y-tv_.y); }

#define C8f 0.70710678118654752f
#define CAf 0.92387953251128676f
#define CBf 0.38268343236508977f

// ---------------- twiddle init ----------------
__global__ void twiddle_init() {
    int k = blockIdx.x * blockDim.x + threadIdx.x;
    if (k < NFFT) {
        double a = -2.0 * M_PI * (double)k / (double)MFFT;
        g_tw[k] = make_float2((float)cos(a), (float)sin(a));
    }
}

// ---------------- fused forward pass 1 (stages 0,1,2): global load + zero pad ----
__device__ __forceinline__ void fwd_pass1_fused(float2* S, int tid, const float2* __restrict__ g) {
#pragma unroll
    for (int it = 0; it < 2; it++) {
        int t = tid + it * 512;           // base = t, r = t
        float2 x[8];
#pragma unroll
        for (int e = 0; e < 4; e++) x[e] = g[t + e * 1024];
        float2 w1 = g_tw[t << 1];
        float2 w2 = csq(w1);
        float2 w4 = csq(w2);
        // stage 0 with zero upper half
        {
            float2 wr1 = cmul(w1, make_float2(C8f, -C8f));
            float2 wr2 = mulni(w1);
            float2 wr3 = cmul(w1, make_float2(-C8f, -C8f));
            x[4] = cmul(x[0], w1);
            x[5] = cmul(x[1], wr1);
            x[6] = cmul(x[2], wr2);
            x[7] = cmul(x[3], wr3);
        }
        // stage 1
        {
            float2 w2n = mulni(w2);
            FBF(x[0], x[2], w2);
            FBF(x[1], x[3], w2n);
            FBF(x[4], x[6], w2);
            FBF(x[5], x[7], w2n);
        }
        // stage 2
        FBF(x[0], x[1], w4);
        FBF(x[2], x[3], w4);
        FBF(x[4], x[5], w4);
        FBF(x[6], x[7], w4);
#pragma unroll
        for (int e = 0; e < 8; e++) S[PHYS(t + e * 1024)] = x[e];
    }
}

// ---------------- grouped forward stages s, s+1, s+2 (s in {3,6}) ----------------
template<int s>
__device__ __forceinline__ void fwd_group3(float2* S, int tid) {
    const int h = 1 << (10 - s);
#pragma unroll
    for (int it = 0; it < 2; it++) {
        int t = tid + it * 512;
        int r = t & (h - 1);
        int base = ((t >> (10 - s)) << (13 - s)) | r;
        float2 x[8];
#pragma unroll
        for (int e = 0; e < 8; e++) x[e] = S[PHYS(base + e * h)];
        float2 w1 = g_tw[r << (s + 1)];
        float2 w2 = csq(w1);
        float2 w4 = csq(w2);
        {
            float2 wr1 = cmul(w1, make_float2(C8f, -C8f));
            float2 wr2 = mulni(w1);
            float2 wr3 = cmul(w1, make_float2(-C8f, -C8f));
            FBF(x[0], x[4], w1);
            FBF(x[1], x[5], wr1);
            FBF(x[2], x[6], wr2);
            FBF(x[3], x[7], wr3);
        }
        {
            float2 w2n = mulni(w2);
            FBF(x[0], x[2], w2);
            FBF(x[1], x[3], w2n);
            FBF(x[4], x[6], w2);
            FBF(x[5], x[7], w2n);
        }
        FBF(x[0], x[1], w4);
        FBF(x[2], x[3], w4);
        FBF(x[4], x[5], w4);
        FBF(x[6], x[7], w4);
#pragma unroll
        for (int e = 0; e < 8; e++) S[PHYS(base + e * h)] = x[e];
    }
}

// ---------------- forward stages 9..12 on 16 consecutive elements ----------------
__device__ __forceinline__ void fwd_group16(float2* S, int tid) {
    float2* row = S + tid * 16;
    int hh = (tid ^ (tid >> 4)) & 15;        // PHYS(16*tid + e) = 16*tid + (e ^ hh)
    float2 x[16];
#pragma unroll
    for (int e = 0; e < 16; e++) x[e] = row[e ^ hh];
    FBF1 (x[0], x[8]);
    FBF  (x[1], x[9],  make_float2( CAf, -CBf));
    FBF  (x[2], x[10], make_float2( C8f, -C8f));
    FBF  (x[3], x[11], make_float2( CBf, -CAf));
    FBFNI(x[4], x[12]);
    FBF  (x[5], x[13], make_float2(-CBf, -CAf));
    FBF  (x[6], x[14], make_float2(-C8f, -C8f));
    FBF  (x[7], x[15], make_float2(-CAf, -CBf));
#pragma unroll
    for (int g = 0; g < 16; g += 8) {
        FBF1 (x[g+0], x[g+4]);
        FBF  (x[g+1], x[g+5], make_float2( C8f, -C8f));
        FBFNI(x[g+2], x[g+6]);
        FBF  (x[g+3], x[g+7], make_float2(-C8f, -C8f));
    }
#pragma unroll
    for (int g = 0; g < 16; g += 4) {
        FBF1 (x[g+0], x[g+2]);
        FBFNI(x[g+1], x[g+3]);
    }
#pragma unroll
    for (int g = 0; g < 16; g += 2) FBF1(x[g], x[g+1]);
#pragma unroll
    for (int e = 0; e < 16; e++) row[e ^ hh] = x[e];
}

// ---------------- inverse stages 0..3 on 16 consecutive elements ----------------
__device__ __forceinline__ void inv_group16(float2* S, int tid) {
    float2* row = S + tid * 16;
    int hh = (tid ^ (tid >> 4)) & 15;
    float2 x[16];
#pragma unroll
    for (int e = 0; e < 16; e++) x[e] = row[e ^ hh];
#pragma unroll
    for (int g = 0; g < 16; g += 2) IBF1(x[g], x[g+1]);
#pragma unroll
    for (int g = 0; g < 16; g += 4) {
        IBF1 (x[g+0], x[g+2]);
        IBFPI(x[g+1], x[g+3]);
    }
#pragma unroll
    for (int g = 0; g < 16; g += 8) {
        IBF1 (x[g+0], x[g+4]);
        IBF  (x[g+1], x[g+5], make_float2( C8f, -C8f));
        IBFPI(x[g+2], x[g+6]);
        IBF  (x[g+3], x[g+7], make_float2(-C8f, -C8f));
    }
    IBF1 (x[0], x[8]);
    IBF  (x[1], x[9],  make_float2( CAf, -CBf));
    IBF  (x[2], x[10], make_float2( C8f, -C8f));
    IBF  (x[3], x[11], make_float2( CBf, -CAf));
    IBFPI(x[4], x[12]);
    IBF  (x[5], x[13], make_float2(-CBf, -CAf));
    IBF  (x[6], x[14], make_float2(-C8f, -C8f));
    IBF  (x[7], x[15], make_float2(-CAf, -CBf));
#pragma unroll
    for (int e = 0; e < 16; e++) row[e ^ hh] = x[e];
}

// ---------------- grouped inverse stages s0, s0+1, s0+2 (s0 in {4,7}) -------
template<int s0>
__device__ __forceinline__ void inv_group3(float2* S, int tid) {
    const int h = 1 << s0;
#pragma unroll
    for (int it = 0; it < 2; it++) {
        int t = tid + it * 512;
        int r = t & (h - 1);
        int base = ((t >> s0) << (s0 + 3)) | r;
        float2 x[8];
#pragma unroll
        for (int e = 0; e < 8; e++) x[e] = S[PHYS(base + e * h)];
        float2 wB = g_tw[r << (11 - s0)];
        float2 wB2 = csq(wB);
        float2 wB4 = csq(wB2);
        IBF(x[0], x[1], wB4);
        IBF(x[2], x[3], wB4);
        IBF(x[4], x[5], wB4);
        IBF(x[6], x[7], wB4);
        {
            float2 w2n = mulni(wB2);
            IBF(x[0], x[2], wB2);
            IBF(x[1], x[3], w2n);
            IBF(x[4], x[6], wB2);
            IBF(x[5], x[7], w2n);
        }
        {
            float2 wr1 = cmul(wB, make_float2(C8f, -C8f));
            float2 wr2 = mulni(wB);
            float2 wr3 = cmul(wB, make_float2(-C8f, -C8f));
            IBF(x[0], x[4], wB);
            IBF(x[1], x[5], wr1);
            IBF(x[2], x[6], wr2);
            IBF(x[3], x[7], wr3);
        }
#pragma unroll
        for (int e = 0; e < 8; e++) S[PHYS(base + e * h)] = x[e];
    }
}

// ---------------- fused inverse final pass (stages 10,11,12) --------------------
__device__ __forceinline__ void inv_pass4_fused(float2* S, int tid,
                                                float2* __restrict__ gdst,
                                                float scale, float bv) {
#pragma unroll
    for (int it = 0; it < 2; it++) {
        int t = tid + it * 512;           // base = t, r = t (s0 = 10)
        float2 x[8];
#pragma unroll
        for (int e = 0; e < 8; e++) x[e] = S[PHYS(t + e * 1024)];
        float2 wB = g_tw[t << 1];
        float2 wB2 = csq(wB);
        float2 wB4 = csq(wB2);
        IBF(x[0], x[1], wB4);
        IBF(x[2], x[3], wB4);
        IBF(x[4], x[5], wB4);
        IBF(x[6], x[7], wB4);
        {
            float2 w2n = mulni(wB2);
            IBF(x[0], x[2], wB2);
            IBF(x[1], x[3], w2n);
            IBF(x[4], x[6], wB2);
            IBF(x[5], x[7], w2n);
        }
        {
            float2 wr1 = cmul(wB, make_float2(C8f, -C8f));
            float2 wr2 = mulni(wB);
            float2 wr3 = cmul(wB, make_float2(-C8f, -C8f));
            float2 t0 = cmulc(x[4], wB);
            float2 t1 = cmulc(x[5], wr1);
            float2 t2 = cmulc(x[6], wr2);
            float2 t3 = cmulc(x[7], wr3);
            x[0] = make_float2(x[0].x + t0.x, x[0].y + t0.y);
            x[1] = make_float2(x[1].x + t1.x, x[1].y + t1.y);
            x[2] = make_float2(x[2].x + t2.x, x[2].y + t2.y);
            x[3] = make_float2(x[3].x + t3.x, x[3].y + t3.y);
        }
#pragma unroll
        for (int e = 0; e < 4; e++)
            gdst[t + e * 1024] = make_float2(x[e].x * scale + bv, x[e].y * scale + bv);
    }
}

// ---------------- implicit filter MLP + modulation, writes g_kT directly --------
// Dynamic smem: hA[16][64], hB[16][64], ktile[768][17]
__global__ void filter_kernel(
    const float* __restrict__ w_in,  const float* __restrict__ b_in,  const float* __restrict__ freq_in,
    const float* __restrict__ w_h0,  const float* __restrict__ b_h0,  const float* __restrict__ freq_h0,
    const float* __restrict__ w_h1,  const float* __restrict__ b_h1,  const float* __restrict__ freq_h1,
    const float* __restrict__ w_out)
{
    extern __shared__ float sm[];
    float* hA    = sm;              // 16*64
    float* hB    = sm + 1024;       // 16*64
    float* ktile = sm + 2048;       // 768*17
    int l0 = blockIdx.x * 16;
    int tid = threadIdx.x;

    for (int idx = tid; idx < 16 * 64; idx += 256) {
        int ll = idx >> 6, j = idx & 63;
        int l = l0 + ll;
        float t0 = (float)l / (float)(SEQ_LEN - 1);
        float ang = (float)(2.0 * M_PI * 1e-4 / (double)SEQ_LEN) * (float)l;
        float z1 = cosf(ang), z2 = -sinf(ang);
        float v = t0 * w_in[j] + z1 * w_in[64 + j] + z2 * w_in[128 + j] + b_in[j];
        hA[ll * 64 + j] = sinf(freq_in[j] * v);
    }
    __syncthreads();
    for (int idx = tid; idx < 16 * 64; idx += 256) {
        int ll = idx >> 6, j = idx & 63;
        float acc = b_h0[j];
#pragma unroll
        for (int i = 0; i < 64; i++) acc += hA[ll * 64 + i] * w_h0[i * 64 + j];
        hB[ll * 64 + j] = sinf(freq_h0[j] * acc);
    }
    __syncthreads();
    for (int idx = tid; idx < 16 * 64; idx += 256) {
        int ll = idx >> 6, j = idx & 63;
        float acc = b_h1[j];
#pragma unroll
        for (int i = 0; i < 64; i++) acc += hB[ll * 64 + i] * w_h1[i * 64 + j];
        hA[ll * 64 + j] = sinf(freq_h1[j] * acc);
    }
    __syncthreads();

    const float MIND = 3.0701134573253943f;
    const float MAXD = 15.350567286626972f;
    for (int ll = 0; ll < 16; ll++) {
        int l = l0 + ll;
        float t0 = (float)l / (float)(SEQ_LEN - 1);
        for (int d = tid; d < HIDDEN; d += 256) {
            float acc = 0.f;
#pragma unroll
            for (int i = 0; i < 64; i++) acc += hA[ll * 64 + i] * w_out[i * HIDDEN + d];
            float ad = MIND + (MAXD - MIND) * ((float)d / 767.0f);
            ktile[d * 17 + ll] = acc * expf(-t0 * ad);
        }
    }
    __syncthreads();

    // write 768 rows of 16 floats each (64 B contiguous per row) as 4x float4
#pragma unroll
    for (int j = 0; j < 3; j++) {
        int row = j * 256 + tid;
        const float* kr = ktile + row * 17;
        float* dst = g_kT + (size_t)row * SEQ_LEN + l0;
        *reinterpret_cast<float4*>(dst)      = make_float4(kr[0],  kr[1],  kr[2],  kr[3]);
        *reinterpret_cast<float4*>(dst + 4)  = make_float4(kr[4],  kr[5],  kr[6],  kr[7]);
        *reinterpret_cast<float4*>(dst + 8)  = make_float4(kr[8],  kr[9],  kr[10], kr[11]);
        *reinterpret_cast<float4*>(dst + 12) = make_float4(kr[12], kr[13], kr[14], kr[15]);
    }
}

// ---------------- transposes: 128(l) x 32(d) per block, float2 on L side --------
__global__ void transpose_in(const float* __restrict__ x) {
    __shared__ float tile[128][33];
    int b = blockIdx.z;
    int l0 = blockIdx.x * 128, d0 = blockIdx.y * 32;
    int tx = threadIdx.x, ty = threadIdx.y;   // (32, 8)
    const float* xb = x + (size_t)b * SEQ_LEN * HIDDEN;
#pragma unroll
    for (int j = 0; j < 16; j++) {
        int ll = j * 8 + ty;
        tile[ll][tx] = xb[(size_t)(l0 + ll) * HIDDEN + d0 + tx];
    }
    __syncthreads();
    float* dst = g_xT + (size_t)(b * HIDDEN + d0) * SEQ_LEN;
    int tid = ty * 32 + tx;
#pragma unroll
    for (int j = 0; j < 8; j++) {
        int idx = j * 256 + tid;   // 0..2047
        int dr = idx >> 6;         // 0..31
        int l2 = idx & 63;         // 0..63
        float2 v = make_float2(tile[2 * l2][dr], tile[2 * l2 + 1][dr]);
        *reinterpret_cast<float2*>(&dst[(size_t)dr * SEQ_LEN + l0 + 2 * l2]) = v;
    }
}

__global__ void transpose_out(float* __restrict__ out) {
    __shared__ float tile[128][33];
    int b = blockIdx.z;
    int l0 = blockIdx.x * 128, d0 = blockIdx.y * 32;
    int tx = threadIdx.x, ty = threadIdx.y;
    const float* src = g_yT + (size_t)(b * HIDDEN + d0) * SEQ_LEN;
    int tid = ty * 32 + tx;
#pragma unroll
    for (int j = 0; j < 8; j++) {
        int idx = j * 256 + tid;
        int dr = idx >> 6;
        int l2 = idx & 63;
        float2 v = *reinterpret_cast<const float2*>(&src[(size_t)dr * SEQ_LEN + l0 + 2 * l2]);
        tile[2 * l2][dr]     = v.x;
        tile[2 * l2 + 1][dr] = v.y;
    }
    __syncthreads();
    float* ob = out + (size_t)b * SEQ_LEN * HIDDEN;
#pragma unroll
    for (int j = 0; j < 16; j++) {
        int ll = j * 8 + ty;
        ob[(size_t)(l0 + ll) * HIDDEN + d0 + tx] = tile[ll][tx];
    }
}

// ---------------- kernel spectrum ----------------
__global__ void __launch_bounds__(512, 3) kf_kernel() {
    extern __shared__ float2 S[];
    int d = blockIdx.x;
    int tid = threadIdx.x;
    const float2* krow = (const float2*)(g_kT + (size_t)d * SEQ_LEN);
    fwd_pass1_fused(S, tid, krow);
    __syncthreads();
    fwd_group3<3>(S, tid); __syncthreads();
    fwd_group3<6>(S, tid); __syncthreads();
    fwd_group16(S, tid);   __syncthreads();

    const float invM = 1.0f / 16384.0f;
    float2* Kf = g_Kf + (size_t)d * (NFFT + 1);
    if (tid == 0) {
        float2 c0 = S[PHYS(0)];
        Kf[0]    = make_float2((c0.x + c0.y) * invM, 0.f);
        Kf[NFFT] = make_float2((c0.x - c0.y) * invM, 0.f);
    }
    for (int t = tid; t < 4096; t += 512) {
        int k  = t + 1;
        int p1 = __brev(k) >> 19;
        int p2 = __brev(8192 - k) >> 19;
        float2 C1 = S[PHYS(p1)], C2 = S[PHYS(p2)];
        float Ex = 0.5f * (C1.x + C2.x), Ey = 0.5f * (C1.y - C2.y);
        float Dx = C1.x - C2.x,          Dy = C1.y + C2.y;
        float Ox = 0.5f * Dy,            Oy = -0.5f * Dx;
        float2 w = g_tw[k];
        float wOx = Ox * w.x - Oy * w.y, wOy = Ox * w.y + Oy * w.x;
        Kf[k]        = make_float2((Ex + wOx) * invM, (Ey + wOy) * invM);
        Kf[8192 - k] = make_float2((Ex - wOx) * invM, -(Ey - wOy) * invM);
    }
}

// ---------------- fused conv ----------------
__global__ void __launch_bounds__(512, 3) conv_kernel(const float* __restrict__ bias) {
    extern __shared__ float2 S[];
    int col = blockIdx.x;           // b*768 + d
    int d   = col % HIDDEN;
    int tid = threadIdx.x;

    const float2* row = (const float2*)(g_xT + (size_t)col * SEQ_LEN);
    fwd_pass1_fused(S, tid, row);
    __syncthreads();
    fwd_group3<3>(S, tid); __syncthreads();
    fwd_group3<6>(S, tid); __syncthreads();
    fwd_group16(S, tid);   __syncthreads();

    const float2* Kf = g_Kf + (size_t)d * (NFFT + 1);
    if (tid == 0) {
        float2 c0 = S[PHYS(0)];
        float U0 = c0.x + c0.y, UN = c0.x - c0.y;
        float2 F0 = Kf[0], FN = Kf[NFFT];
        float2 Y0 = make_float2(U0 * F0.x, U0 * F0.y);
        float2 YN = make_float2(UN * FN.x, UN * FN.y);
        float Eyx = 0.5f * (Y0.x + YN.x), Eyy = 0.5f * (Y0.y + YN.y);
        float Dyx = 0.5f * (Y0.x - YN.x), Dyy = 0.5f * (Y0.y - YN.y);
        S[PHYS(0)] = make_float2(Eyx - Dyy, Eyy + Dyx);
    }
    for (int t = tid; t < 4096; t += 512) {
        int k  = t + 1;
        int k2 = 8192 - k;
        int p1 = __brev(k)  >> 19;
        int p2 = __brev(k2) >> 19;
        int q1 = PHYS(p1), q2 = PHYS(p2);
        float2 C1 = S[q1], C2 = S[q2];
        float Ex = 0.5f * (C1.x + C2.x), Ey = 0.5f * (C1.y - C2.y);
        float Dx = C1.x - C2.x,          Dy = C1.y + C2.y;
        float Ox = 0.5f * Dy,            Oy = -0.5f * Dx;
        float2 w = g_tw[k];
        float wOx = Ox * w.x - Oy * w.y, wOy = Ox * w.y + Oy * w.x;
        float2 Uk  = make_float2(Ex + wOx, Ey + wOy);
        float2 UkN = make_float2(Ex - wOx, Ey - wOy);
        float2 F1 = Kf[k];
        float2 F2 = Kf[k2];
        float2 Y1 = cmul(Uk, F1);
        float2 Y2 = cmul(UkN, make_float2(F2.x, -F2.y));
        float2 Eyc = make_float2(0.5f * (Y1.x + Y2.x), 0.5f * (Y1.y + Y2.y));
        float2 Dyc = make_float2(0.5f * (Y1.x - Y2.x), 0.5f * (Y1.y - Y2.y));
        float2 Oyc = make_float2(Dyc.x * w.x + Dyc.y * w.y, Dyc.y * w.x - Dyc.x * w.y);
        float2 Zk  = make_float2(Eyc.x - Oyc.y, Eyc.y + Oyc.x);
        // mirror bin: w2 = g_tw[8192-k] = (-w.x, w.y)
        float2 Y1p = cmul(make_float2(UkN.x, -UkN.y), F2);
        float2 Y2p = cmul(make_float2(Uk.x, -Uk.y), make_float2(F1.x, -F1.y));
        float2 w2  = make_float2(-w.x, w.y);
        float2 Eyp = make_float2(0.5f * (Y1p.x + Y2p.x), 0.5f * (Y1p.y + Y2p.y));
        float2 Dyp = make_float2(0.5f * (Y1p.x - Y2p.x), 0.5f * (Y1p.y - Y2p.y));
        float2 Oyp = make_float2(Dyp.x * w2.x + Dyp.y * w2.y, Dyp.y * w2.x - Dyp.x * w2.y);
        float2 Zk2 = make_float2(Eyp.x - Oyp.y, Eyp.y + Oyp.x);
        S[q1] = Zk;
        S[q2] = Zk2;
    }
    __syncthreads();

    inv_group16(S, tid);   __syncthreads();
    inv_group3<4>(S, tid); __syncthreads();
    inv_group3<7>(S, tid); __syncthreads();

    const float invN = 1.0f / 8192.0f;
    float bv = bias[d];
    float2* orow = (float2*)(g_yT + (size_t)col * SEQ_LEN);
    inv_pass4_fused(S, tid, orow, invN, bv);
}

// ---------------- launch ----------------
extern "C" void kernel_launch(void* const* d_in, const int* in_sizes, int n_in,
                              void* d_out, int out_size) {
    const float* x       = (const float*)d_in[0];
    const float* w_in    = (const float*)d_in[1];
    const float* b_in    = (const float*)d_in[2];
    const float* freq_in = (const float*)d_in[3];
    const float* w_h0    = (const float*)d_in[4];
    const float* b_h0    = (const float*)d_in[5];
    const float* freq_h0 = (const float*)d_in[6];
    const float* w_h1    = (const float*)d_in[7];
    const float* b_h1    = (const float*)d_in[8];
    const float* freq_h1 = (const float*)d_in[9];
    const float* w_out   = (const float*)d_in[10];
    const float* bias    = (const float*)d_in[11];
    float* out = (float*)d_out;

    const int FILTER_SMEM = (2048 + 768 * 17) * 4;   // 60416 B

    cudaFuncSetAttribute(kf_kernel,     cudaFuncAttributeMaxDynamicSharedMemorySize, SMEM_BYTES);
    cudaFuncSetAttribute(conv_kernel,   cudaFuncAttributeMaxDynamicSharedMemorySize, SMEM_BYTES);
    cudaFuncSetAttribute(filter_kernel, cudaFuncAttributeMaxDynamicSharedMemorySize, FILTER_SMEM);

    // Fork a side stream for transpose_in (independent of the filter/kf chain).
    // Created during the single captured call; the graph retains the dependency
    // structure, so replays need no host-side stream state.
    cudaStream_t s2;
    cudaStreamCreateWithFlags(&s2, cudaStreamNonBlocking);
    cudaEvent_t evFork, evJoin;
    cudaEventCreateWithFlags(&evFork, cudaEventDisableTiming);
    cudaEventCreateWithFlags(&evJoin, cudaEventDisableTiming);

    // fork point on the (capturing) default stream
    cudaEventRecord(evFork, 0);
    cudaStreamWaitEvent(s2, evFork, 0);

    // branch A (default stream): filter chain -> kf
    twiddle_init<<<16, 512>>>();
    filter_kernel<<<SEQ_LEN / 16, 256, FILTER_SMEM>>>(w_in, b_in, freq_in, w_h0, b_h0, freq_h0,
                                                      w_h1, b_h1, freq_h1, w_out);
    kf_kernel<<<HIDDEN, 512, SMEM_BYTES>>>();

    // branch B (s2): input transpose
    dim3 tblk(32, 8);
    dim3 tgrid(SEQ_LEN / 128, HIDDEN / 32, BATCH);
    transpose_in<<<tgrid, tblk, 0, s2>>>(x);
    cudaEventRecord(evJoin, s2);

    // join: conv needs both branches
    cudaStreamWaitEvent(0, evJoin, 0);
    conv_kernel<<<BATCH * HIDDEN, 512, SMEM_BYTES>>>(bias);
    transpose_out<<<tgrid, tblk>>>(out);
}

// round 16
// speedup vs baseline: 1.5985x; 1.0357x over previous
#include <cuda_runtime.h>
#include <math.h>

#define SEQ_LEN 8192
#define HIDDEN  768
#define BATCH   8
#define NFFT    8192     // packed complex FFT size
#define MFFT    16384    // real FFT size
#define SMEM_BYTES (NFFT * 8)   // 65536

// ---------------- static scratch (allocation-free rule) ----------------
__device__ float2 g_tw[NFFT];                         // exp(-2*pi*i*k/16384)
__device__ float  g_kT[HIDDEN * SEQ_LEN];             // filter transposed (D, L)
__device__ float2 g_Kf[HIDDEN * (NFFT + 1)];          // rfft(k)/16384 per d
__device__ float  g_xT[(size_t)BATCH * HIDDEN * SEQ_LEN];  // x transposed (B*D, L)
__device__ float  g_yT[(size_t)BATCH * HIDDEN * SEQ_LEN];  // y transposed (B*D, L)

__device__ __forceinline__ float2 cmul(float2 a, float2 b) {
    return make_float2(a.x * b.x - a.y * b.y, a.x * b.y + a.y * b.x);
}
__device__ __forceinline__ float2 cmulc(float2 a, float2 b) {   // a * conj(b)
    return make_float2(a.x * b.x + a.y * b.y, a.y * b.x - a.x * b.y);
}
__device__ __forceinline__ float2 csq(float2 a) {
    return make_float2(a.x * a.x - a.y * a.y, 2.0f * a.x * a.y);
}
__device__ __forceinline__ float2 mulni(float2 a) {  // a * (-i)
    return make_float2(a.y, -a.x);
}
// XOR-swizzled physical index: conflict-free for strided FFT passes and
// 2-way worst case for the bit-reversed pointwise pass.
__device__ __forceinline__ int PHYS(int i) {
    return (i & ~15) | ((i ^ (i >> 4) ^ (i >> 8)) & 15);
}

#define FBF(a, b, w) { float2 u_=(a), v_=(b); (a)=make_float2(u_.x+v_.x,u_.y+v_.y); \
                       float2 d_=make_float2(u_.x-v_.x,u_.y-v_.y); (b)=cmul(d_, (w)); }
#define FBF1(a, b)   { float2 u_=(a), v_=(b); (a)=make_float2(u_.x+v_.x,u_.y+v_.y); \
                       (b)=make_float2(u_.x-v_.x,u_.y-v_.y); }
#define FBFNI(a, b)  { float2 u_=(a), v_=(b); (a)=make_float2(u_.x+v_.x,u_.y+v_.y); \
                       (b)=make_float2(u_.y-v_.y, -(u_.x-v_.x)); }
#define IBF(a, b, w) { float2 u_=(a); float2 tv_=cmulc((b),(w)); \
                       (a)=make_float2(u_.x+tv_.x,u_.y+tv_.y); (b)=make_float2(u_.x-tv_.x,u_.y-tv_.y); }
#define IBF1(a, b)   FBF1(a, b)
#define IBFPI(a, b)  { float2 u_=(a), v_=(b); float2 tv_=make_float2(-v_.y, v_.x); \
                       (a)=make_float2(u_.x+tv_.x,u_.y+tv_.y); (b)=make_float2(u_.x-tv_.x,u_.y-tv_.y); }

#define C8f 0.70710678118654752f
#define CAf 0.92387953251128676f
#define CBf 0.38268343236508977f

// ---------------- twiddle init ----------------
__global__ void twiddle_init() {
    int k = blockIdx.x * blockDim.x + threadIdx.x;
    if (k < NFFT) {
        double a = -2.0 * M_PI * (double)k / (double)MFFT;
        g_tw[k] = make_float2((float)cos(a), (float)sin(a));
    }
}

// ---------------- fused forward pass 1 (stages 0,1,2): global load + zero pad ----
__device__ __forceinline__ void fwd_pass1_fused(float2* S, int tid, const float2* __restrict__ g) {
#pragma unroll
    for (int it = 0; it < 2; it++) {
        int t = tid + it * 512;           // base = t, r = t
        float2 x[8];
#pragma unroll
        for (int e = 0; e < 4; e++) x[e] = g[t + e * 1024];
        float2 w1 = g_tw[t << 1];
        float2 w2 = csq(w1);
        float2 w4 = csq(w2);
        // stage 0 with zero upper half
        {
            float2 wr1 = cmul(w1, make_float2(C8f, -C8f));
            float2 wr2 = mulni(w1);
            float2 wr3 = cmul(w1, make_float2(-C8f, -C8f));
            x[4] = cmul(x[0], w1);
            x[5] = cmul(x[1], wr1);
            x[6] = cmul(x[2], wr2);
            x[7] = cmul(x[3], wr3);
        }
        // stage 1
        {
            float2 w2n = mulni(w2);
            FBF(x[0], x[2], w2);
            FBF(x[1], x[3], w2n);
            FBF(x[4], x[6], w2);
            FBF(x[5], x[7], w2n);
        }
        // stage 2
        FBF(x[0], x[1], w4);
        FBF(x[2], x[3], w4);
        FBF(x[4], x[5], w4);
        FBF(x[6], x[7], w4);
#pragma unroll
        for (int e = 0; e < 8; e++) S[PHYS(t + e * 1024)] = x[e];
    }
}

// ---------------- grouped forward stages s, s+1, s+2 (s in {3,6}) ----------------
template<int s>
__device__ __forceinline__ void fwd_group3(float2* S, int tid) {
    const int h = 1 << (10 - s);
#pragma unroll
    for (int it = 0; it < 2; it++) {
        int t = tid + it * 512;
        int r = t & (h - 1);
        int base = ((t >> (10 - s)) << (13 - s)) | r;
        float2 x[8];
#pragma unroll
        for (int e = 0; e < 8; e++) x[e] = S[PHYS(base + e * h)];
        float2 w1 = g_tw[r << (s + 1)];
        float2 w2 = csq(w1);
        float2 w4 = csq(w2);
        {
            float2 wr1 = cmul(w1, make_float2(C8f, -C8f));
            float2 wr2 = mulni(w1);
            float2 wr3 = cmul(w1, make_float2(-C8f, -C8f));
            FBF(x[0], x[4], w1);
            FBF(x[1], x[5], wr1);
            FBF(x[2], x[6], wr2);
            FBF(x[3], x[7], wr3);
        }
        {
            float2 w2n = mulni(w2);
            FBF(x[0], x[2], w2);
            FBF(x[1], x[3], w2n);
            FBF(x[4], x[6], w2);
            FBF(x[5], x[7], w2n);
        }
        FBF(x[0], x[1], w4);
        FBF(x[2], x[3], w4);
        FBF(x[4], x[5], w4);
        FBF(x[6], x[7], w4);
#pragma unroll
        for (int e = 0; e < 8; e++) S[PHYS(base + e * h)] = x[e];
    }
}

// ---------------- forward stages 9..12 on 16 consecutive elements ----------------
__device__ __forceinline__ void fwd_group16(float2* S, int tid) {
    float2* row = S + tid * 16;
    int hh = (tid ^ (tid >> 4)) & 15;        // PHYS(16*tid + e) = 16*tid + (e ^ hh)
    float2 x[16];
#pragma unroll
    for (int e = 0; e < 16; e++) x[e] = row[e ^ hh];
    FBF1 (x[0], x[8]);
    FBF  (x[1], x[9],  make_float2( CAf, -CBf));
    FBF  (x[2], x[10], make_float2( C8f, -C8f));
    FBF  (x[3], x[11], make_float2( CBf, -CAf));
    FBFNI(x[4], x[12]);
    FBF  (x[5], x[13], make_float2(-CBf, -CAf));
    FBF  (x[6], x[14], make_float2(-C8f, -C8f));
    FBF  (x[7], x[15], make_float2(-CAf, -CBf));
#pragma unroll
    for (int g = 0; g < 16; g += 8) {
        FBF1 (x[g+0], x[g+4]);
        FBF  (x[g+1], x[g+5], make_float2( C8f, -C8f));
        FBFNI(x[g+2], x[g+6]);
        FBF  (x[g+3], x[g+7], make_float2(-C8f, -C8f));
    }
#pragma unroll
    for (int g = 0; g < 16; g += 4) {
        FBF1 (x[g+0], x[g+2]);
        FBFNI(x[g+1], x[g+3]);
    }
#pragma unroll
    for (int g = 0; g < 16; g += 2) FBF1(x[g], x[g+1]);
#pragma unroll
    for (int e = 0; e < 16; e++) row[e ^ hh] = x[e];
}

// ---------------- inverse stages 0..3 on 16 consecutive elements ----------------
__device__ __forceinline__ void inv_group16(float2* S, int tid) {
    float2* row = S + tid * 16;
    int hh = (tid ^ (tid >> 4)) & 15;
    float2 x[16];
#pragma unroll
    for (int e = 0; e < 16; e++) x[e] = row[e ^ hh];
#pragma unroll
    for (int g = 0; g < 16; g += 2) IBF1(x[g], x[g+1]);
#pragma unroll
    for (int g = 0; g < 16; g += 4) {
        IBF1 (x[g+0], x[g+2]);
        IBFPI(x[g+1], x[g+3]);
    }
#pragma unroll
    for (int g = 0; g < 16; g += 8) {
        IBF1 (x[g+0], x[g+4]);
        IBF  (x[g+1], x[g+5], make_float2( C8f, -C8f));
        IBFPI(x[g+2], x[g+6]);
        IBF  (x[g+3], x[g+7], make_float2(-C8f, -C8f));
    }
    IBF1 (x[0], x[8]);
    IBF  (x[1], x[9],  make_float2( CAf, -CBf));
    IBF  (x[2], x[10], make_float2( C8f, -C8f));
    IBF  (x[3], x[11], make_float2( CBf, -CAf));
    IBFPI(x[4], x[12]);
    IBF  (x[5], x[13], make_float2(-CBf, -CAf));
    IBF  (x[6], x[14], make_float2(-C8f, -C8f));
    IBF  (x[7], x[15], make_float2(-CAf, -CBf));
#pragma unroll
    for (int e = 0; e < 16; e++) row[e ^ hh] = x[e];
}

// ---------------- grouped inverse stages s0, s0+1, s0+2 (s0 in {4,7}) -------
template<int s0>
__device__ __forceinline__ void inv_group3(float2* S, int tid) {
    const int h = 1 << s0;
#pragma unroll
    for (int it = 0; it < 2; it++) {
        int t = tid + it * 512;
        int r = t & (h - 1);
        int base = ((t >> s0) << (s0 + 3)) | r;
        float2 x[8];
#pragma unroll
        for (int e = 0; e < 8; e++) x[e] = S[PHYS(base + e * h)];
        float2 wB = g_tw[r << (11 - s0)];
        float2 wB2 = csq(wB);
        float2 wB4 = csq(wB2);
        IBF(x[0], x[1], wB4);
        IBF(x[2], x[3], wB4);
        IBF(x[4], x[5], wB4);
        IBF(x[6], x[7], wB4);
        {
            float2 w2n = mulni(wB2);
            IBF(x[0], x[2], wB2);
            IBF(x[1], x[3], w2n);
            IBF(x[4], x[6], wB2);
            IBF(x[5], x[7], w2n);
        }
        {
            float2 wr1 = cmul(wB, make_float2(C8f, -C8f));
            float2 wr2 = mulni(wB);
            float2 wr3 = cmul(wB, make_float2(-C8f, -C8f));
            IBF(x[0], x[4], wB);
            IBF(x[1], x[5], wr1);
            IBF(x[2], x[6], wr2);
            IBF(x[3], x[7], wr3);
        }
#pragma unroll
        for (int e = 0; e < 8; e++) S[PHYS(base + e * h)] = x[e];
    }
}

// ---------------- fused inverse final pass (stages 10,11,12) --------------------
__device__ __forceinline__ void inv_pass4_fused(float2* S, int tid,
                                                float2* __restrict__ gdst,
                                                float scale, float bv) {
#pragma unroll
    for (int it = 0; it < 2; it++) {
        int t = tid + it * 512;           // base = t, r = t (s0 = 10)
        float2 x[8];
#pragma unroll
        for (int e = 0; e < 8; e++) x[e] = S[PHYS(t + e * 1024)];
        float2 wB = g_tw[t << 1];
        float2 wB2 = csq(wB);
        float2 wB4 = csq(wB2);
        IBF(x[0], x[1], wB4);
        IBF(x[2], x[3], wB4);
        IBF(x[4], x[5], wB4);
        IBF(x[6], x[7], wB4);
        {
            float2 w2n = mulni(wB2);
            IBF(x[0], x[2], wB2);
            IBF(x[1], x[3], w2n);
            IBF(x[4], x[6], wB2);
            IBF(x[5], x[7], w2n);
        }
        {
            float2 wr1 = cmul(wB, make_float2(C8f, -C8f));
            float2 wr2 = mulni(wB);
            float2 wr3 = cmul(wB, make_float2(-C8f, -C8f));
            float2 t0 = cmulc(x[4], wB);
            float2 t1 = cmulc(x[5], wr1);
            float2 t2 = cmulc(x[6], wr2);
            float2 t3 = cmulc(x[7], wr3);
            x[0] = make_float2(x[0].x + t0.x, x[0].y + t0.y);
            x[1] = make_float2(x[1].x + t1.x, x[1].y + t1.y);
            x[2] = make_float2(x[2].x + t2.x, x[2].y + t2.y);
            x[3] = make_float2(x[3].x + t3.x, x[3].y + t3.y);
        }
#pragma unroll
        for (int e = 0; e < 4; e++)
            gdst[t + e * 1024] = make_float2(x[e].x * scale + bv, x[e].y * scale + bv);
    }
}

// ---------------- implicit filter MLP + modulation, writes g_kT directly --------
// Dynamic smem: hA[16][64], hB[16][64], ktile[768][17]
__global__ void filter_kernel(
    const float* __restrict__ w_in,  const float* __restrict__ b_in,  const float* __restrict__ freq_in,
    const float* __restrict__ w_h0,  const float* __restrict__ b_h0,  const float* __restrict__ freq_h0,
    const float* __restrict__ w_h1,  const float* __restrict__ b_h1,  const float* __restrict__ freq_h1,
    const float* __restrict__ w_out)
{
    extern __shared__ float sm[];
    float* hA    = sm;              // 16*64
    float* hB    = sm + 1024;       // 16*64
    float* ktile = sm + 2048;       // 768*17
    int l0 = blockIdx.x * 16;
    int tid = threadIdx.x;

    for (int idx = tid; idx < 16 * 64; idx += 256) {
        int ll = idx >> 6, j = idx & 63;
        int l = l0 + ll;
        float t0 = (float)l / (float)(SEQ_LEN - 1);
        float ang = (float)(2.0 * M_PI * 1e-4 / (double)SEQ_LEN) * (float)l;
        float z1 = cosf(ang), z2 = -sinf(ang);
        float v = t0 * w_in[j] + z1 * w_in[64 + j] + z2 * w_in[128 + j] + b_in[j];
        hA[ll * 64 + j] = sinf(freq_in[j] * v);
    }
    __syncthreads();
    for (int idx = tid; idx < 16 * 64; idx += 256) {
        int ll = idx >> 6, j = idx & 63;
        float acc = b_h0[j];
#pragma unroll
        for (int i = 0; i < 64; i++) acc += hA[ll * 64 + i] * w_h0[i * 64 + j];
        hB[ll * 64 + j] = sinf(freq_h0[j] * acc);
    }
    __syncthreads();
    for (int idx = tid; idx < 16 * 64; idx += 256) {
        int ll = idx >> 6, j = idx & 63;
        float acc = b_h1[j];
#pragma unroll
        for (int i = 0; i < 64; i++) acc += hB[ll * 64 + i] * w_h1[i * 64 + j];
        hA[ll * 64 + j] = sinf(freq_h1[j] * acc);
    }
    __syncthreads();

    const float MIND = 3.0701134573253943f;
    const float MAXD = 15.350567286626972f;
    for (int ll = 0; ll < 16; ll++) {
        int l = l0 + ll;
        float t0 = (float)l / (float)(SEQ_LEN - 1);
        for (int d = tid; d < HIDDEN; d += 256) {
            float acc = 0.f;
#pragma unroll
            for (int i = 0; i < 64; i++) acc += hA[ll * 64 + i] * w_out[i * HIDDEN + d];
            float ad = MIND + (MAXD - MIND) * ((float)d / 767.0f);
            ktile[d * 17 + ll] = acc * expf(-t0 * ad);
        }
    }
    __syncthreads();

    // write 768 rows of 16 floats each (64 B contiguous per row) as 4x float4
#pragma unroll
    for (int j = 0; j < 3; j++) {
        int row = j * 256 + tid;
        const float* kr = ktile + row * 17;
        float* dst = g_kT + (size_t)row * SEQ_LEN + l0;
        *reinterpret_cast<float4*>(dst)      = make_float4(kr[0],  kr[1],  kr[2],  kr[3]);
        *reinterpret_cast<float4*>(dst + 4)  = make_float4(kr[4],  kr[5],  kr[6],  kr[7]);
        *reinterpret_cast<float4*>(dst + 8)  = make_float4(kr[8],  kr[9],  kr[10], kr[11]);
        *reinterpret_cast<float4*>(dst + 12) = make_float4(kr[12], kr[13], kr[14], kr[15]);
    }
}

// ---------------- transposes: 128(l) x 32(d) per block, float2 on L side --------
// Chunked variants: b = b0 + blockIdx.z (grid z = chunk size).
__global__ void transpose_in(const float* __restrict__ x, int b0) {
    __shared__ float tile[128][33];
    int b = b0 + blockIdx.z;
    int l0 = blockIdx.x * 128, d0 = blockIdx.y * 32;
    int tx = threadIdx.x, ty = threadIdx.y;   // (32, 8)
    const float* xb = x + (size_t)b * SEQ_LEN * HIDDEN;
#pragma unroll
    for (int j = 0; j < 16; j++) {
        int ll = j * 8 + ty;
        tile[ll][tx] = xb[(size_t)(l0 + ll) * HIDDEN + d0 + tx];
    }
    __syncthreads();
    float* dst = g_xT + (size_t)(b * HIDDEN + d0) * SEQ_LEN;
    int tid = ty * 32 + tx;
#pragma unroll
    for (int j = 0; j < 8; j++) {
        int idx = j * 256 + tid;   // 0..2047
        int dr = idx >> 6;         // 0..31
        int l2 = idx & 63;         // 0..63
        float2 v = make_float2(tile[2 * l2][dr], tile[2 * l2 + 1][dr]);
        *reinterpret_cast<float2*>(&dst[(size_t)dr * SEQ_LEN + l0 + 2 * l2]) = v;
    }
}

__global__ void transpose_out(float* __restrict__ out, int b0) {
    __shared__ float tile[128][33];
    int b = b0 + blockIdx.z;
    int l0 = blockIdx.x * 128, d0 = blockIdx.y * 32;
    int tx = threadIdx.x, ty = threadIdx.y;
    const float* src = g_yT + (size_t)(b * HIDDEN + d0) * SEQ_LEN;
    int tid = ty * 32 + tx;
#pragma unroll
    for (int j = 0; j < 8; j++) {
        int idx = j * 256 + tid;
        int dr = idx >> 6;
        int l2 = idx & 63;
        float2 v = *reinterpret_cast<const float2*>(&src[(size_t)dr * SEQ_LEN + l0 + 2 * l2]);
        tile[2 * l2][dr]     = v.x;
        tile[2 * l2 + 1][dr] = v.y;
    }
    __syncthreads();
    float* ob = out + (size_t)b * SEQ_LEN * HIDDEN;
#pragma unroll
    for (int j = 0; j < 16; j++) {
        int ll = j * 8 + ty;
        ob[(size_t)(l0 + ll) * HIDDEN + d0 + tx] = tile[ll][tx];
    }
}

// ---------------- kernel spectrum ----------------
__global__ void __launch_bounds__(512, 3) kf_kernel() {
    extern __shared__ float2 S[];
    int d = blockIdx.x;
    int tid = threadIdx.x;
    const float2* krow = (const float2*)(g_kT + (size_t)d * SEQ_LEN);
    fwd_pass1_fused(S, tid, krow);
    __syncthreads();
    fwd_group3<3>(S, tid); __syncthreads();
    fwd_group3<6>(S, tid); __syncthreads();
    fwd_group16(S, tid);   __syncthreads();

    const float invM = 1.0f / 16384.0f;
    float2* Kf = g_Kf + (size_t)d * (NFFT + 1);
    if (tid == 0) {
        float2 c0 = S[PHYS(0)];
        Kf[0]    = make_float2((c0.x + c0.y) * invM, 0.f);
        Kf[NFFT] = make_float2((c0.x - c0.y) * invM, 0.f);
    }
    for (int t = tid; t < 4096; t += 512) {
        int k  = t + 1;
        int p1 = __brev(k) >> 19;
        int p2 = __brev(8192 - k) >> 19;
        float2 C1 = S[PHYS(p1)], C2 = S[PHYS(p2)];
        float Ex = 0.5f * (C1.x + C2.x), Ey = 0.5f * (C1.y - C2.y);
        float Dx = C1.x - C2.x,          Dy = C1.y + C2.y;
        float Ox = 0.5f * Dy,            Oy = -0.5f * Dx;
        float2 w = g_tw[k];
        float wOx = Ox * w.x - Oy * w.y, wOy = Ox * w.y + Oy * w.x;
        Kf[k]        = make_float2((Ex + wOx) * invM, (Ey + wOy) * invM);
        Kf[8192 - k] = make_float2((Ex - wOx) * invM, -(Ey - wOy) * invM);
    }
}

// ---------------- fused conv (chunked: grid (768, chunk), b = b0 + blockIdx.y) ---
__global__ void __launch_bounds__(512, 3) conv_kernel(const float* __restrict__ bias, int b0) {
    extern __shared__ float2 S[];
    int d   = blockIdx.x;
    int b   = b0 + blockIdx.y;
    int col = b * HIDDEN + d;
    int tid = threadIdx.x;

    const float2* row = (const float2*)(g_xT + (size_t)col * SEQ_LEN);
    fwd_pass1_fused(S, tid, row);
    __syncthreads();
    fwd_group3<3>(S, tid); __syncthreads();
    fwd_group3<6>(S, tid); __syncthreads();
    fwd_group16(S, tid);   __syncthreads();

    const float2* Kf = g_Kf + (size_t)d * (NFFT + 1);
    if (tid == 0) {
        float2 c0 = S[PHYS(0)];
        float U0 = c0.x + c0.y, UN = c0.x - c0.y;
        float2 F0 = Kf[0], FN = Kf[NFFT];
        float2 Y0 = make_float2(U0 * F0.x, U0 * F0.y);
        float2 YN = make_float2(UN * FN.x, UN * FN.y);
        float Eyx = 0.5f * (Y0.x + YN.x), Eyy = 0.5f * (Y0.y + YN.y);
        float Dyx = 0.5f * (Y0.x - YN.x), Dyy = 0.5f * (Y0.y - YN.y);
        S[PHYS(0)] = make_float2(Eyx - Dyy, Eyy + Dyx);
    }
    for (int t = tid; t < 4096; t += 512) {
        int k  = t + 1;
        int k2 = 8192 - k;
        int p1 = __brev(k)  >> 19;
        int p2 = __brev(k2) >> 19;
        int q1 = PHYS(p1), q2 = PHYS(p2);
        float2 C1 = S[q1], C2 = S[q2];
        float Ex = 0.5f * (C1.x + C2.x), Ey = 0.5f * (C1.y - C2.y);
        float Dx = C1.x - C2.x,          Dy = C1.y + C2.y;
        float Ox = 0.5f * Dy,            Oy = -0.5f * Dx;
        float2 w = g_tw[k];
        float wOx = Ox * w.x - Oy * w.y, wOy = Ox * w.y + Oy * w.x;
        float2 Uk  = make_float2(Ex + wOx, Ey + wOy);
        float2 UkN = make_float2(Ex - wOx, Ey - wOy);
        float2 F1 = Kf[k];
        float2 F2 = Kf[k2];
        float2 Y1 = cmul(Uk, F1);
        float2 Y2 = cmul(UkN, make_float2(F2.x, -F2.y));
        float2 Eyc = make_float2(0.5f * (Y1.x + Y2.x), 0.5f * (Y1.y + Y2.y));
        float2 Dyc = make_float2(0.5f * (Y1.x - Y2.x), 0.5f * (Y1.y - Y2.y));
        float2 Oyc = make_float2(Dyc.x * w.x + Dyc.y * w.y, Dyc.y * w.x - Dyc.x * w.y);
        float2 Zk  = make_float2(Eyc.x - Oyc.y, Eyc.y + Oyc.x);
        // mirror bin: w2 = g_tw[8192-k] = (-w.x, w.y)
        float2 Y1p = cmul(make_float2(UkN.x, -UkN.y), F2);
        float2 Y2p = cmul(make_float2(Uk.x, -Uk.y), make_float2(F1.x, -F1.y));
        float2 w2  = make_float2(-w.x, w.y);
        float2 Eyp = make_float2(0.5f * (Y1p.x + Y2p.x), 0.5f * (Y1p.y + Y2p.y));
        float2 Dyp = make_float2(0.5f * (Y1p.x - Y2p.x), 0.5f * (Y1p.y - Y2p.y));
        float2 Oyp = make_float2(Dyp.x * w2.x + Dyp.y * w2.y, Dyp.y * w2.x - Dyp.x * w2.y);
        float2 Zk2 = make_float2(Eyp.x - Oyp.y, Eyp.y + Oyp.x);
        S[q1] = Zk;
        S[q2] = Zk2;
    }
    __syncthreads();

    inv_group16(S, tid);   __syncthreads();
    inv_group3<4>(S, tid); __syncthreads();
    inv_group3<7>(S, tid); __syncthreads();

    const float invN = 1.0f / 8192.0f;
    float bv = bias[d];
    float2* orow = (float2*)(g_yT + (size_t)col * SEQ_LEN);
    inv_pass4_fused(S, tid, orow, invN, bv);
}

// ---------------- launch: 2-stream chunked pipeline (1 extra stream only) -------
extern "C" void kernel_launch(void* const* d_in, const int* in_sizes, int n_in,
                              void* d_out, int out_size) {
    const float* x       = (const float*)d_in[0];
    const float* w_in    = (const float*)d_in[1];
    const float* b_in    = (const float*)d_in[2];
    const float* freq_in = (const float*)d_in[3];
    const float* w_h0    = (const float*)d_in[4];
    const float* b_h0    = (const float*)d_in[5];
    const float* freq_h0 = (const float*)d_in[6];
    const float* w_h1    = (const float*)d_in[7];
    const float* b_h1    = (const float*)d_in[8];
    const float* freq_h1 = (const float*)d_in[9];
    const float* w_out   = (const float*)d_in[10];
    const float* bias    = (const float*)d_in[11];
    float* out = (float*)d_out;

    const int FILTER_SMEM = (2048 + 768 * 17) * 4;   // 60416 B
    const int CH = 2;                                // batches per chunk (4 chunks)

    cudaFuncSetAttribute(kf_kernel,     cudaFuncAttributeMaxDynamicSharedMemorySize, SMEM_BYTES);
    cudaFuncSetAttribute(conv_kernel,   cudaFuncAttributeMaxDynamicSharedMemorySize, SMEM_BYTES);
    cudaFuncSetAttribute(filter_kernel, cudaFuncAttributeMaxDynamicSharedMemorySize, FILTER_SMEM);

    // One extra stream (round-14 proven footprint) + sync-only events.
    cudaStream_t s2;
    cudaStreamCreateWithFlags(&s2, cudaStreamNonBlocking);
    cudaEvent_t evFork, evKf, evTin[4], evC[4], evDone;
    cudaEventCreateWithFlags(&evFork, cudaEventDisableTiming);
    cudaEventCreateWithFlags(&evKf,   cudaEventDisableTiming);
    cudaEventCreateWithFlags(&evDone, cudaEventDisableTiming);
    for (int c = 0; c < 4; c++) {
        cudaEventCreateWithFlags(&evTin[c], cudaEventDisableTiming);
        cudaEventCreateWithFlags(&evC[c],   cudaEventDisableTiming);
    }

    dim3 tblk(32, 8);
    dim3 tgrid(SEQ_LEN / 128, HIDDEN / 32, CH);
    dim3 cgrid(HIDDEN, CH);

    // fork
    cudaEventRecord(evFork, 0);
    cudaStreamWaitEvent(s2, evFork, 0);

    // stream 0: filter chain -> kf
    twiddle_init<<<16, 512>>>();
    filter_kernel<<<SEQ_LEN / 16, 256, FILTER_SMEM>>>(w_in, b_in, freq_in, w_h0, b_h0, freq_h0,
                                                      w_h1, b_h1, freq_h1, w_out);
    kf_kernel<<<HIDDEN, 512, SMEM_BYTES>>>();
    cudaEventRecord(evKf, 0);

    // s2: input transposes for all 4 chunks
    for (int c = 0; c < 4; c++) {
        transpose_in<<<tgrid, tblk, 0, s2>>>(x, c * CH);
        cudaEventRecord(evTin[c], s2);
    }

    // conv chunks: 0,2 on stream 0; 1,3 on s2 (backfill across streams)
    cudaStreamWaitEvent(0, evTin[0], 0);
    conv_kernel<<<cgrid, 512, SMEM_BYTES>>>(bias, 0 * CH);
    cudaEventRecord(evC[0], 0);

    cudaStreamWaitEvent(s2, evKf, 0);
    conv_kernel<<<cgrid, 512, SMEM_BYTES, s2>>>(bias, 1 * CH);
    cudaEventRecord(evC[1], s2);

    cudaStreamWaitEvent(0, evTin[2], 0);
    conv_kernel<<<cgrid, 512, SMEM_BYTES>>>(bias, 2 * CH);
    cudaEventRecord(evC[2], 0);

    conv_kernel<<<cgrid, 512, SMEM_BYTES, s2>>>(bias, 3 * CH);
    cudaEventRecord(evC[3], s2);

    // output transposes: chunk 1,3 on stream 0; chunk 0,2 on s2
    cudaStreamWaitEvent(0, evC[1], 0);
    transpose_out<<<tgrid, tblk>>>(out, 1 * CH);
    cudaStreamWaitEvent(s2, evC[0], 0);
    transpose_out<<<tgrid, tblk, 0, s2>>>(out, 0 * CH);
    cudaStreamWaitEvent(0, evC[3], 0);
    transpose_out<<<tgrid, tblk>>>(out, 3 * CH);
    cudaStreamWaitEvent(s2, evC[2], 0);
    transpose_out<<<tgrid, tblk, 0, s2>>>(out, 2 * CH);

    // join s2 back into stream 0
    cudaEventRecord(evDone, s2);
    cudaStreamWaitEvent(0, evDone, 0);
}